// round 7
// baseline (speedup 1.0000x reference)
#include <cuda_runtime.h>

// ---------------------------------------------------------------------------
// WaveNet Mel2Raw — tf32 mma.sync, deferred skip, cp.async DMA staging of
// pre-rounded tf32 activation copies (bit-identical numerics to r6).
// ---------------------------------------------------------------------------

namespace {

constexpr int Bn  = 2;
constexpr int Ln  = 32512;
constexpr int Rn  = 64;
constexpr int Sn  = 128;
constexpr int NMn = 80;
constexpr int NCn = 256;
constexpr int NBn = 30;

constexpr int AP = 136;   // smem pitch (x4B); 136*4=544 B, 16B-aligned rows

// ---- packed tf32 weight buffer (A fragments) ----
constexpr int PK_DIL_BLK  = 16384;
constexpr int PK_DIL_TAP  = 8192;
constexpr int OFF_DIL     = 0;
constexpr int PK_COND_BLK = 10240;
constexpr int OFF_COND    = 491520;
constexpr int PK_SKIP_BLK = 8192;
constexpr int OFF_SKIP    = 798720;
constexpr int PK_RES_BLK  = 4096;
constexpr int OFF_RES     = 1044480;
constexpr int OFF_P1      = 1167360;
constexpr int OFF_P2      = 1200128;
constexpr int PK_TOTAL    = 1265664;

__device__ unsigned g_pk[PK_TOTAL];
__device__ float    g_bs_sum[Sn];

__device__ unsigned g_condU[Bn * NMn * Ln];     // tf32 bits of cond
__device__ float    g_resA[Bn * Rn  * Ln];      // fp32 res carry (double buffer)
__device__ float    g_resB[Bn * Rn  * Ln];
__device__ unsigned g_resTFA[Bn * Rn * Ln];     // tf32 bits of res (double buffer)
__device__ unsigned g_resTFB[Bn * Rn * Ln];
__device__ unsigned g_h[NBn * Bn * Rn * Ln];    // tf32 bits of gate outputs

__device__ __forceinline__ float ex2f(float x) {
    float y; asm("ex2.approx.f32 %0, %1;" : "=f"(y) : "f"(x)); return y;
}
__device__ __forceinline__ float rcpf(float x) {
    float y; asm("rcp.approx.f32 %0, %1;" : "=f"(y) : "f"(x)); return y;
}
__device__ __forceinline__ float gate_fn(float f, float g) {
    float ef = ex2f(2.8853900817779268f * f);
    float th = 1.0f - 2.0f * rcpf(ef + 1.0f);
    float sg = rcpf(1.0f + ex2f(-1.4426950408889634f * g));
    return th * sg;
}
__device__ __forceinline__ unsigned f2tf(float x) {
    unsigned u; asm("cvt.rna.tf32.f32 %0, %1;" : "=r"(u) : "f"(x)); return u;
}

__device__ __forceinline__ void cp16(unsigned* s, const unsigned* g) {
    unsigned sa = (unsigned)__cvta_generic_to_shared(s);
    asm volatile("cp.async.ca.shared.global [%0], [%1], 16;" :: "r"(sa), "l"(g));
}
__device__ __forceinline__ void cp4(unsigned* s, const unsigned* g) {
    unsigned sa = (unsigned)__cvta_generic_to_shared(s);
    asm volatile("cp.async.ca.shared.global [%0], [%1], 4;" :: "r"(sa), "l"(g));
}
__device__ __forceinline__ void cp_commit() {
    asm volatile("cp.async.commit_group;");
}
__device__ __forceinline__ void cp_wait0() {
    asm volatile("cp.async.wait_group 0;");
}

__device__ __forceinline__ void mma8(float c[4], const unsigned a[4], const unsigned b[2]) {
    asm volatile(
        "mma.sync.aligned.m16n8k8.row.col.f32.tf32.tf32.f32 "
        "{%0,%1,%2,%3},{%4,%5,%6,%7},{%8,%9},{%0,%1,%2,%3};"
        : "+f"(c[0]), "+f"(c[1]), "+f"(c[2]), "+f"(c[3])
        : "r"(a[0]), "r"(a[1]), "r"(a[2]), "r"(a[3]), "r"(b[0]), "r"(b[1]));
}

// Two M-16 tiles (second at pkA + miStride), warp N tile = 64.
__device__ __forceinline__ void gemm_p2s(
    float acc[2][8][4], const unsigned* __restrict__ sB, int pitch,
    int rowbase, int nk, const uint4* __restrict__ pkA, int miStride,
    int lane, int n0, int gid, int tig)
{
    #pragma unroll
    for (int ks = 0; ks < nk; ks++) {
        uint4 va0 = pkA[ks * 32 + lane];
        uint4 va1 = pkA[miStride + ks * 32 + lane];
        unsigned A0[4] = {va0.x, va0.y, va0.z, va0.w};
        unsigned A1[4] = {va1.x, va1.y, va1.z, va1.w};
        const unsigned* b0 = sB + (rowbase + ks * 8 + tig) * pitch + n0 + gid;
        const unsigned* b1 = b0 + 4 * pitch;
        #pragma unroll
        for (int j = 0; j < 8; j++) {
            unsigned bf[2] = { b0[j * 8], b1[j * 8] };
            mma8(acc[0][j], A0, bf);
            mma8(acc[1][j], A1, bf);
        }
    }
}

// Single M-16 tile.
__device__ __forceinline__ void gemm_p1(
    float acc[8][4], const unsigned* __restrict__ sB, int pitch,
    int nk, const uint4* __restrict__ pkA,
    int lane, int n0, int gid, int tig)
{
    #pragma unroll
    for (int ks = 0; ks < nk; ks++) {
        uint4 va = pkA[ks * 32 + lane];
        unsigned A[4] = {va.x, va.y, va.z, va.w};
        const unsigned* b0 = sB + (ks * 8 + tig) * pitch + n0 + gid;
        const unsigned* b1 = b0 + 4 * pitch;
        #pragma unroll
        for (int j = 0; j < 8; j++) {
            unsigned bf[2] = { b0[j * 8], b1[j * 8] };
            mma8(acc[j], A, bf);
        }
    }
}

// ---------------------------------------------------------------------------
// prep: pack weights into tf32 A-fragment order + skip-bias sum
// ---------------------------------------------------------------------------
__device__ __forceinline__ uint4 pack_frag(const float* __restrict__ src,
                                           int as, int am, int ao,
                                           int nk, int idx4)
{
    const int mt   = idx4 / (nk * 32);
    const int rem  = idx4 % (nk * 32);
    const int ks   = rem >> 5;
    const int lane = rem & 31;
    const int gid  = lane >> 2, tig = lane & 3;
    const int r = mt * 16 + gid;
    const int k = ks * 8 + tig;
    uint4 v;
    v.x = f2tf(src[r * as + k * am + ao]);
    v.y = f2tf(src[(r + 8) * as + k * am + ao]);
    v.z = f2tf(src[r * as + (k + 4) * am + ao]);
    v.w = f2tf(src[(r + 8) * as + (k + 4) * am + ao]);
    return v;
}

__global__ void prep_kernel(
    const float* __restrict__ dil_w,  const float* __restrict__ cond_w,
    const float* __restrict__ skip_w, const float* __restrict__ res_w,
    const float* __restrict__ p1_w,   const float* __restrict__ p2_w,
    const float* __restrict__ skip_b)
{
    uint4* pk = (uint4*)g_pk;
    const int stride = gridDim.x * blockDim.x;
    const int g0 = blockIdx.x * blockDim.x + threadIdx.x;
    if (g0 < Sn) {
        float s = 0.0f;
        for (int i = 0; i < NBn; i++) s += skip_b[i * Sn + g0];
        g_bs_sum[g0] = s;
    }
    for (int q = g0; q < PK_TOTAL / 4; q += stride) {
        uint4 v;
        if (q < OFF_COND / 4) {
            const int blk = q / (PK_DIL_BLK / 4), r2 = q % (PK_DIL_BLK / 4);
            const int tap = r2 / (PK_DIL_TAP / 4), idx4 = r2 % (PK_DIL_TAP / 4);
            v = pack_frag(dil_w + blk * 16384, 128, 2, tap, 8, idx4);
        } else if (q < OFF_SKIP / 4) {
            const int q2 = q - OFF_COND / 4;
            const int blk = q2 / (PK_COND_BLK / 4), idx4 = q2 % (PK_COND_BLK / 4);
            v = pack_frag(cond_w + blk * (128 * NMn), NMn, 1, 0, 10, idx4);
        } else if (q < OFF_RES / 4) {
            const int q2 = q - OFF_SKIP / 4;
            const int blk = q2 / (PK_SKIP_BLK / 4), idx4 = q2 % (PK_SKIP_BLK / 4);
            v = pack_frag(skip_w + blk * (Sn * Rn), 64, 1, 0, 8, idx4);
        } else if (q < OFF_P1 / 4) {
            const int q2 = q - OFF_RES / 4;
            const int blk = q2 / (PK_RES_BLK / 4), idx4 = q2 % (PK_RES_BLK / 4);
            v = pack_frag(res_w + blk * (Rn * Rn), 64, 1, 0, 8, idx4);
        } else if (q < OFF_P2 / 4) {
            v = pack_frag(p1_w, 128, 1, 0, 16, q - OFF_P1 / 4);
        } else {
            v = pack_frag(p2_w, 256, 1, 0, 32, q - OFF_P2 / 4);
        }
        pk[q] = v;
    }
}

// ---------------------------------------------------------------------------
// cond: transposed conv -> 2 taps; stores tf32 bits directly
// ---------------------------------------------------------------------------
__global__ __launch_bounds__(256) void cond_kernel(
    const float* __restrict__ mels, const float* __restrict__ mel_w,
    const float* __restrict__ mel_b)
{
    __shared__ float m0s[NMn], m1s[NMn];
    const int b  = blockIdx.y;
    const int t0 = blockIdx.x * 128;
    const int q  = t0 >> 8;
    const int tid = threadIdx.x;
    if (tid < NMn) {
        m0s[tid] = mels[(b * NMn + tid) * 128 + q];
        m1s[tid] = mels[(b * NMn + tid) * 128 + q + 1];
    }
    __syncthreads();
    for (int j = tid; j < NMn * 128; j += 256) {
        const int c  = j >> 7;
        const int tt = j & 127;
        const int t  = t0 + tt;
        const int r  = t & 255;
        const float* w = mel_w + c * (NMn * 512);
        float acc = mel_b[c];
        #pragma unroll 4
        for (int ci = 0; ci < NMn; ci++) {
            acc += w[ci * 512 + 255 - r] * m0s[ci];
            acc += w[ci * 512 + 511 - r] * m1s[ci];
        }
        g_condU[(b * NMn + c) * Ln + t] = f2tf(acc);
    }
}

__global__ void init_kernel(const float* __restrict__ x,
                            const float* __restrict__ iw,
                            const float* __restrict__ ib)
{
    const int stride = gridDim.x * blockDim.x;
    const int tid0   = blockIdx.x * blockDim.x + threadIdx.x;
    for (int i = tid0; i < Bn * Rn * Ln; i += stride) {
        const int t = i % Ln;
        const int r = (i / Ln) % Rn;
        const int b = i / (Ln * Rn);
        const float v = iw[r] * x[b * Ln + t] + ib[r];
        g_resA[i]   = v;
        g_resTFA[i] = f2tf(v);
    }
}

// ---------------------------------------------------------------------------
// Block kernel: cp.async staging -> z-GEMM -> gate -> h + res update
// 256 threads, 8 warps (4M x 2N), tile 128co x 128t
// ---------------------------------------------------------------------------
constexpr int BLK_SMEM = 208 * AP * 4;   // 113152 B -> 2 CTAs/SM

__global__ __launch_bounds__(256, 2) void block_kernel(
    const float* __restrict__ dil_b, const float* __restrict__ cond_b,
    const float* __restrict__ res_b,
    const float* __restrict__ res_in, float* __restrict__ res_out,
    const unsigned* __restrict__ resTF_in, unsigned* __restrict__ resTF_out,
    int blk)
{
    extern __shared__ unsigned smu[];
    unsigned* s_act = smu;                 // rows: 0-63 prev, 64-127 cur, 128-207 cond
    unsigned* s_h   = smu;                 // rows 0-63 reused for h (tf32)

    const int d = 1 << (blk % 10);
    const float* bd = dil_b  + blk * 128;
    const float* bc = cond_b + blk * 128;
    const float* br = res_b  + blk * Rn;

    const int b   = blockIdx.y;
    const int t0  = blockIdx.x * 128;
    const int tid = threadIdx.x;

    // ---- stage activations via cp.async (tf32 bits, no conversion) ----
    const unsigned* rtf = resTF_in + b * (Rn * Ln);
    for (int i = tid; i < 64 * 32; i += 256) {
        const int ci = i >> 5, v = (i & 31) * 4;
        cp16(s_act + (64 + ci) * AP + v, rtf + ci * Ln + t0 + v);
    }
    const unsigned* cu = g_condU + b * (NMn * Ln);
    for (int i = tid; i < NMn * 32; i += 256) {
        const int ci = i >> 5, v = (i & 31) * 4;
        cp16(s_act + (128 + ci) * AP + v, cu + ci * Ln + t0 + v);
    }
    if (t0 >= d) {
        const unsigned* rp = rtf + t0 - d;
        if ((d & 3) == 0) {
            for (int i = tid; i < 64 * 32; i += 256) {
                const int ci = i >> 5, v = (i & 31) * 4;
                cp16(s_act + ci * AP + v, rp + ci * Ln + v);
            }
        } else {
            for (int i = tid; i < 64 * 128; i += 256) {
                const int ci = i >> 7, tt = i & 127;
                cp4(s_act + ci * AP + tt, rp + ci * Ln + tt);
            }
        }
    } else {
        for (int i = tid; i < 64 * 128; i += 256) {
            const int ci = i >> 7, tt = i & 127;
            const int tp = t0 + tt - d;
            if (tp >= 0) cp4(s_act + ci * AP + tt, rtf + ci * Ln + tp);
            else         s_act[ci * AP + tt] = 0u;
        }
    }
    cp_commit();
    cp_wait0();
    __syncthreads();

    const int lane = tid & 31, warp = tid >> 5;
    const int gid = lane >> 2, tig = lane & 3;
    const int mw = warp & 3;
    const int n0 = (warp >> 2) * 64;
    const int m0f = mw * 16;

    // ---- GEMM1: acc[0] = f rows, acc[1] = g rows ----
    float acc[2][8][4];
    {
        const int rf = m0f + gid, rg = rf + 64;
        const float f0 = bd[rf] + bc[rf],       f1 = bd[rf + 8] + bc[rf + 8];
        const float g0 = bd[rg] + bc[rg],       g1 = bd[rg + 8] + bc[rg + 8];
        #pragma unroll
        for (int j = 0; j < 8; j++) {
            acc[0][j][0] = f0; acc[0][j][1] = f0; acc[0][j][2] = f1; acc[0][j][3] = f1;
            acc[1][j][0] = g0; acc[1][j][1] = g0; acc[1][j][2] = g1; acc[1][j][3] = g1;
        }
    }
    const uint4* pk_dil = (const uint4*)(g_pk + OFF_DIL + blk * PK_DIL_BLK);
    const uint4* pk_c   = (const uint4*)(g_pk + OFF_COND + blk * PK_COND_BLK);
    gemm_p2s(acc, s_act, AP,   0,  8, pk_dil + mw * 256,        4 * 256, lane, n0, gid, tig);
    gemm_p2s(acc, s_act, AP,  64,  8, pk_dil + 2048 + mw * 256, 4 * 256, lane, n0, gid, tig);
    gemm_p2s(acc, s_act, AP, 128, 10, pk_c + mw * 320,          4 * 320, lane, n0, gid, tig);

    __syncthreads();   // all GEMM1 smem reads complete

    // ---- gate in registers -> h (tf32) rows 0-63 ----
    {
        const int r0 = m0f + gid, r1 = r0 + 8;
        #pragma unroll
        for (int j = 0; j < 8; j++) {
            const int c = n0 + j * 8 + tig * 2;
            s_h[r0 * AP + c]     = f2tf(gate_fn(acc[0][j][0], acc[1][j][0]));
            s_h[r0 * AP + c + 1] = f2tf(gate_fn(acc[0][j][1], acc[1][j][1]));
            s_h[r1 * AP + c]     = f2tf(gate_fn(acc[0][j][2], acc[1][j][2]));
            s_h[r1 * AP + c + 1] = f2tf(gate_fn(acc[0][j][3], acc[1][j][3]));
        }
    }
    __syncthreads();

    // ---- write h to global (coalesced uint4) ----
    {
        unsigned* ho = g_h + (size_t)(blk * Bn + b) * (Rn * Ln) + t0;
        for (int i = tid; i < 64 * 32; i += 256) {
            const int row = i >> 5, q = (i & 31) * 4;
            *(uint4*)(ho + row * Ln + q) = *(const uint4*)(s_h + row * AP + q);
        }
    }

    // ---- GEMM3: res_out = res_in + Wr*h + br (M=64, K=64) ----
    float accr[8][4];
    const int mr = mw * 16;
    {
        const int r0 = mr + gid;
        const float z0 = br[r0], z1 = br[r0 + 8];
        #pragma unroll
        for (int j = 0; j < 8; j++) {
            accr[j][0] = z0; accr[j][1] = z0;
            accr[j][2] = z1; accr[j][3] = z1;
        }
    }
    const uint4* pk_r = (const uint4*)(g_pk + OFF_RES + blk * PK_RES_BLK);
    gemm_p1(accr, s_h, AP, 8, pk_r + (mr >> 4) * 256, lane, n0, gid, tig);

    {
        float*    rob = res_out   + b * (Rn * Ln) + t0;
        unsigned* rtb = resTF_out + b * (Rn * Ln) + t0;
        const float* rib = res_in + b * (Rn * Ln) + t0;
        const int r0 = mr + gid;
        #pragma unroll
        for (int j = 0; j < 8; j++) {
            const int c = n0 + j * 8 + tig * 2;
            float v00 = rib[r0 * Ln + c]           + accr[j][0];
            float v01 = rib[r0 * Ln + c + 1]       + accr[j][1];
            float v10 = rib[(r0 + 8) * Ln + c]     + accr[j][2];
            float v11 = rib[(r0 + 8) * Ln + c + 1] + accr[j][3];
            rob[r0 * Ln + c]           = v00;
            rob[r0 * Ln + c + 1]       = v01;
            rob[(r0 + 8) * Ln + c]     = v10;
            rob[(r0 + 8) * Ln + c + 1] = v11;
            rtb[r0 * Ln + c]           = f2tf(v00);
            rtb[r0 * Ln + c + 1]       = f2tf(v01);
            rtb[(r0 + 8) * Ln + c]     = f2tf(v10);
            rtb[(r0 + 8) * Ln + c + 1] = f2tf(v11);
        }
    }
}

// ---------------------------------------------------------------------------
// Tail kernel: skip = bias_sum + sum_i Ws_i h_i (K=1920, cp.async pipelined)
//              -> relu -> p1 (K=128) -> relu -> p2 (K=256) -> out
// ---------------------------------------------------------------------------
constexpr int SP_SMEM = (128 * AP + 256 * AP) * 4;   // 208896 B

__global__ __launch_bounds__(256, 1) void sp_kernel(
    const float* __restrict__ b1, const float* __restrict__ b2,
    float* __restrict__ out)
{
    extern __shared__ unsigned smu[];
    unsigned* s_hb  = smu;                 // two h buffers [64][AP] each
    unsigned* s_sk  = smu;                 // reuse: relu(skip) tf32 [128][AP]
    unsigned* s_y1  = smu + 128 * AP;      // relu(y1) tf32 [256][AP]

    const int b   = blockIdx.y;
    const int t0  = blockIdx.x * 128;
    const int tid = threadIdx.x;
    const int lane = tid & 31, warp = tid >> 5;
    const int gid = lane >> 2, tig = lane & 3;
    const int mw = warp & 3;
    const int n0 = (warp >> 2) * 64;

    // ---- Phase A: skip accumulation over 30 layers ----
    const int m0s = mw * 32;
    float acc[2][8][4];
    {
        const int r0 = m0s + gid;
        const float z0 = g_bs_sum[r0],      z1 = g_bs_sum[r0 + 8];
        const float z2 = g_bs_sum[r0 + 16], z3 = g_bs_sum[r0 + 24];
        #pragma unroll
        for (int j = 0; j < 8; j++) {
            acc[0][j][0] = z0; acc[0][j][1] = z0; acc[0][j][2] = z1; acc[0][j][3] = z1;
            acc[1][j][0] = z2; acc[1][j][1] = z2; acc[1][j][2] = z3; acc[1][j][3] = z3;
        }
    }

    // preload h_0 into buffer 0
    {
        const unsigned* hp = g_h + (size_t)(0 * Bn + b) * (Rn * Ln) + t0;
        for (int i = tid; i < 64 * 32; i += 256) {
            const int row = i >> 5, q = (i & 31) * 4;
            cp16(s_hb + row * AP + q, hp + row * Ln + q);
        }
        cp_commit();
        cp_wait0();
    }
    __syncthreads();

    const uint4* pk_s0 = (const uint4*)(g_pk + OFF_SKIP) + (m0s >> 4) * 256;
    for (int i = 0; i < NBn; i++) {
        if (i + 1 < NBn) {
            const unsigned* hp = g_h + (size_t)((i + 1) * Bn + b) * (Rn * Ln) + t0;
            unsigned* dst = s_hb + ((i + 1) & 1) * (64 * AP);
            for (int k = tid; k < 64 * 32; k += 256) {
                const int row = k >> 5, q = (k & 31) * 4;
                cp16(dst + row * AP + q, hp + row * Ln + q);
            }
            cp_commit();
        }
        gemm_p2s(acc, s_hb + (i & 1) * (64 * AP), AP, 0, 8,
                 pk_s0 + i * (PK_SKIP_BLK / 4), 256, lane, n0, gid, tig);
        cp_wait0();
        __syncthreads();
    }

    // ---- Phase B: relu(skip) -> tf32 staging rows [128][AP] ----
    #pragma unroll
    for (int mi = 0; mi < 2; mi++) {
        const int r0 = m0s + mi * 16 + gid;
        #pragma unroll
        for (int j = 0; j < 8; j++) {
            const int c = n0 + j * 8 + tig * 2;
            s_sk[r0 * AP + c]           = f2tf(fmaxf(acc[mi][j][0], 0.0f));
            s_sk[r0 * AP + c + 1]       = f2tf(fmaxf(acc[mi][j][1], 0.0f));
            s_sk[(r0 + 8) * AP + c]     = f2tf(fmaxf(acc[mi][j][2], 0.0f));
            s_sk[(r0 + 8) * AP + c + 1] = f2tf(fmaxf(acc[mi][j][3], 0.0f));
        }
    }
    __syncthreads();

    // ---- Phase C: p1 (M=256, K=128) -> relu -> s_y1 ----
    const int m0p = warp * 32;
    const uint4* pkP1 = (const uint4*)(g_pk + OFF_P1) + (m0p >> 4) * 512;
    #pragma unroll
    for (int nh = 0; nh < 2; nh++) {
        const int nn = nh * 64;
        {
            const int r0 = m0p + gid;
            const float z0 = b1[r0], z1 = b1[r0 + 8];
            const float z2 = b1[r0 + 16], z3 = b1[r0 + 24];
            #pragma unroll
            for (int j = 0; j < 8; j++) {
                acc[0][j][0] = z0; acc[0][j][1] = z0; acc[0][j][2] = z1; acc[0][j][3] = z1;
                acc[1][j][0] = z2; acc[1][j][1] = z2; acc[1][j][2] = z3; acc[1][j][3] = z3;
            }
        }
        gemm_p2s(acc, s_sk, AP, 0, 16, pkP1, 512, lane, nn, gid, tig);
        #pragma unroll
        for (int mi = 0; mi < 2; mi++) {
            const int r0 = m0p + mi * 16 + gid;
            #pragma unroll
            for (int j = 0; j < 8; j++) {
                const int c = nn + j * 8 + tig * 2;
                s_y1[r0 * AP + c]           = f2tf(fmaxf(acc[mi][j][0], 0.0f));
                s_y1[r0 * AP + c + 1]       = f2tf(fmaxf(acc[mi][j][1], 0.0f));
                s_y1[(r0 + 8) * AP + c]     = f2tf(fmaxf(acc[mi][j][2], 0.0f));
                s_y1[(r0 + 8) * AP + c + 1] = f2tf(fmaxf(acc[mi][j][3], 0.0f));
            }
        }
    }
    __syncthreads();

    // ---- Phase D: p2 (M=256, K=256) -> out ----
    const uint4* pkP2 = (const uint4*)(g_pk + OFF_P2) + (m0p >> 4) * 1024;
    float* ob = out + (size_t)b * (NCn * Ln) + t0;
    #pragma unroll
    for (int nh = 0; nh < 2; nh++) {
        const int nn = nh * 64;
        {
            const int r0 = m0p + gid;
            const float z0 = b2[r0], z1 = b2[r0 + 8];
            const float z2 = b2[r0 + 16], z3 = b2[r0 + 24];
            #pragma unroll
            for (int j = 0; j < 8; j++) {
                acc[0][j][0] = z0; acc[0][j][1] = z0; acc[0][j][2] = z1; acc[0][j][3] = z1;
                acc[1][j][0] = z2; acc[1][j][1] = z2; acc[1][j][2] = z3; acc[1][j][3] = z3;
            }
        }
        gemm_p2s(acc, s_y1, AP, 0, 32, pkP2, 1024, lane, nn, gid, tig);
        #pragma unroll
        for (int mi = 0; mi < 2; mi++) {
            const int r0 = m0p + mi * 16 + gid;
            #pragma unroll
            for (int j = 0; j < 8; j++) {
                const int c = nn + j * 8 + tig * 2;
                float* p = ob + r0 * Ln + c;
                p[0] = acc[mi][j][0]; p[1] = acc[mi][j][1];
                float* q = ob + (r0 + 8) * Ln + c;
                q[0] = acc[mi][j][2]; q[1] = acc[mi][j][3];
            }
        }
    }
}

} // anonymous namespace

// ---------------------------------------------------------------------------
extern "C" void kernel_launch(void* const* d_in, const int* in_sizes, int n_in,
                              void* d_out, int out_size)
{
    (void)in_sizes; (void)n_in; (void)out_size;
    const float* x          = (const float*)d_in[0];
    const float* mels       = (const float*)d_in[1];
    const float* input_w    = (const float*)d_in[2];
    const float* input_b    = (const float*)d_in[3];
    const float* mel_w      = (const float*)d_in[4];
    const float* mel_b      = (const float*)d_in[5];
    const float* blk_dil_w  = (const float*)d_in[6];
    const float* blk_dil_b  = (const float*)d_in[7];
    const float* blk_cond_w = (const float*)d_in[8];
    const float* blk_cond_b = (const float*)d_in[9];
    const float* blk_skip_w = (const float*)d_in[10];
    const float* blk_skip_b = (const float*)d_in[11];
    const float* blk_res_w  = (const float*)d_in[12];
    const float* blk_res_b  = (const float*)d_in[13];
    const float* post1_w    = (const float*)d_in[14];
    const float* post1_b    = (const float*)d_in[15];
    const float* post2_w    = (const float*)d_in[16];
    const float* post2_b    = (const float*)d_in[17];

    cudaFuncSetAttribute(block_kernel, cudaFuncAttributeMaxDynamicSharedMemorySize, BLK_SMEM);
    cudaFuncSetAttribute(sp_kernel,    cudaFuncAttributeMaxDynamicSharedMemorySize, SP_SMEM);

    float* resA; cudaGetSymbolAddress((void**)&resA, g_resA);
    float* resB; cudaGetSymbolAddress((void**)&resB, g_resB);
    unsigned* rtA; cudaGetSymbolAddress((void**)&rtA, g_resTFA);
    unsigned* rtB; cudaGetSymbolAddress((void**)&rtB, g_resTFB);

    prep_kernel<<<1024, 256>>>(blk_dil_w, blk_cond_w, blk_skip_w, blk_res_w,
                               post1_w, post2_w, blk_skip_b);
    cond_kernel<<<dim3(Ln / 128, Bn), 256>>>(mels, mel_w, mel_b);
    init_kernel<<<512, 256>>>(x, input_w, input_b);

    for (int i = 0; i < NBn; i++) {
        const float*    rin  = (i & 1) ? resB : resA;
        float*          rout = (i & 1) ? resA : resB;
        const unsigned* tin  = (i & 1) ? rtB : rtA;
        unsigned*       tout = (i & 1) ? rtA : rtB;
        block_kernel<<<dim3(Ln / 128, Bn), 256, BLK_SMEM>>>(
            blk_dil_b, blk_cond_b, blk_res_b, rin, rout, tin, tout, i);
    }

    sp_kernel<<<dim3(Ln / 128, Bn), 256, SP_SMEM>>>(post1_b, post2_b, (float*)d_out);
}

// round 10
// speedup vs baseline: 1.4306x; 1.4306x over previous
#include <cuda_runtime.h>
#include <cuda_fp16.h>

// ---------------------------------------------------------------------------
// WaveNet Mel2Raw — fp16 mma.m16n8k16 (fp32 accum), deferred skip,
// channel-pair-interleaved half2 activation layout, cp.async DMA staging.
// ---------------------------------------------------------------------------

namespace {

constexpr int Bn  = 2;
constexpr int Ln  = 32512;
constexpr int Rn  = 64;
constexpr int Sn  = 128;
constexpr int NMn = 80;
constexpr int NCn = 256;
constexpr int NBn = 30;

constexpr int AP = 136;   // smem pitch in 32-bit words

// ---- packed fp16 weight buffer (A fragments, 32-bit words) ----
constexpr int PK_DIL_BLK  = 8192;      // 2 taps x 8 mt x 4 ks x 128
constexpr int PK_DIL_TAP  = 4096;
constexpr int OFF_DIL     = 0;         // 30 * 8192 = 245760
constexpr int PK_COND_BLK = 5120;      // 8 mt x 5 ks x 128
constexpr int OFF_COND    = 245760;
constexpr int PK_SKIP_BLK = 4096;      // 8 mt x 4 ks x 128
constexpr int OFF_SKIP    = 399360;
constexpr int PK_RES_BLK  = 2048;      // 4 mt x 4 ks x 128
constexpr int OFF_RES     = 522240;
constexpr int OFF_P1      = 583680;    // 16 mt x 8 ks x 128 = 16384
constexpr int OFF_P2      = 600064;    // 16 mt x 16 ks x 128 = 32768
constexpr int PK_TOTAL    = 632832;

__device__ unsigned g_pk[PK_TOTAL];
__device__ float    g_bs_sum[Sn];

// channel-pair-interleaved half2 activations: word[c2][t] = (ch 2*c2, ch 2*c2+1)
__device__ unsigned g_condH[Bn * (NMn/2) * Ln];
__device__ float    g_res  [Bn * Rn * Ln];        // fp32 carry (double buffer)
__device__ float    g_resB [Bn * Rn * Ln];
__device__ unsigned g_resHA[Bn * (Rn/2) * Ln];
__device__ unsigned g_resHB[Bn * (Rn/2) * Ln];
__device__ unsigned g_hH   [NBn * Bn * (Rn/2) * Ln];  // ~250 MB

__device__ __forceinline__ float ex2f(float x) {
    float y; asm("ex2.approx.f32 %0, %1;" : "=f"(y) : "f"(x)); return y;
}
__device__ __forceinline__ float rcpf(float x) {
    float y; asm("rcp.approx.f32 %0, %1;" : "=f"(y) : "f"(x)); return y;
}
__device__ __forceinline__ float gate_fn(float f, float g) {
    float ef = ex2f(2.8853900817779268f * f);
    float th = 1.0f - 2.0f * rcpf(ef + 1.0f);
    float sg = rcpf(1.0f + ex2f(-1.4426950408889634f * g));
    return th * sg;
}
// pack two floats -> half2 word (lo = first arg = even channel)
__device__ __forceinline__ unsigned pack2(float a, float b) {
    __half2 h = __floats2half2_rn(a, b);
    return *(unsigned*)&h;
}

__device__ __forceinline__ void cp16(unsigned* s, const unsigned* g) {
    unsigned sa = (unsigned)__cvta_generic_to_shared(s);
    asm volatile("cp.async.ca.shared.global [%0], [%1], 16;" :: "r"(sa), "l"(g));
}
__device__ __forceinline__ void cp8(unsigned* s, const unsigned* g) {
    unsigned sa = (unsigned)__cvta_generic_to_shared(s);
    asm volatile("cp.async.ca.shared.global [%0], [%1], 8;" :: "r"(sa), "l"(g));
}
__device__ __forceinline__ void cp4(unsigned* s, const unsigned* g) {
    unsigned sa = (unsigned)__cvta_generic_to_shared(s);
    asm volatile("cp.async.ca.shared.global [%0], [%1], 4;" :: "r"(sa), "l"(g));
}
__device__ __forceinline__ void cp_commit() { asm volatile("cp.async.commit_group;"); }
__device__ __forceinline__ void cp_wait0()  { asm volatile("cp.async.wait_group 0;"); }

// fp16 mma m16n8k16, fp32 accumulate (in place)
__device__ __forceinline__ void mmah(float c[4], const unsigned a[4], const unsigned b[2]) {
    asm volatile(
        "mma.sync.aligned.m16n8k16.row.col.f32.f16.f16.f32 "
        "{%0,%1,%2,%3},{%4,%5,%6,%7},{%8,%9},{%0,%1,%2,%3};"
        : "+f"(c[0]), "+f"(c[1]), "+f"(c[2]), "+f"(c[3])
        : "r"(a[0]), "r"(a[1]), "r"(a[2]), "r"(a[3]), "r"(b[0]), "r"(b[1]));
}

// Two M-16 tiles (second at pkA + miStride uint4s), warp N tile = 64.
__device__ __forceinline__ void gemm_h2(
    float acc[2][8][4], const unsigned* __restrict__ sB, int pitch,
    int rb, int nk, const uint4* __restrict__ pkA, int miStride,
    int lane, int n0, int gid, int tig)
{
    #pragma unroll
    for (int ks = 0; ks < nk; ks++) {
        uint4 va0 = pkA[ks * 32 + lane];
        uint4 va1 = pkA[miStride + ks * 32 + lane];
        unsigned A0[4] = {va0.x, va0.y, va0.z, va0.w};
        unsigned A1[4] = {va1.x, va1.y, va1.z, va1.w};
        const unsigned* b0 = sB + (rb + ks * 8 + tig) * pitch + n0 + gid;
        const unsigned* b1 = b0 + 4 * pitch;
        #pragma unroll
        for (int j = 0; j < 8; j++) {
            unsigned bf[2] = { b0[j * 8], b1[j * 8] };
            mmah(acc[0][j], A0, bf);
            mmah(acc[1][j], A1, bf);
        }
    }
}

// Single M-16 tile.
__device__ __forceinline__ void gemm_h1(
    float acc[8][4], const unsigned* __restrict__ sB, int pitch,
    int rb, int nk, const uint4* __restrict__ pkA,
    int lane, int n0, int gid, int tig)
{
    #pragma unroll
    for (int ks = 0; ks < nk; ks++) {
        uint4 va = pkA[ks * 32 + lane];
        unsigned A[4] = {va.x, va.y, va.z, va.w};
        const unsigned* b0 = sB + (rb + ks * 8 + tig) * pitch + n0 + gid;
        const unsigned* b1 = b0 + 4 * pitch;
        #pragma unroll
        for (int j = 0; j < 8; j++) {
            unsigned bf[2] = { b0[j * 8], b1[j * 8] };
            mmah(acc[j], A, bf);
        }
    }
}

// ---------------------------------------------------------------------------
// prep: pack weights into fp16 A fragments with row permutation
// phi: mma row gid -> channel mt*16 + 2*gid; row gid+8 -> +1
// ---------------------------------------------------------------------------
__device__ __forceinline__ uint4 pack_frag_h(const float* __restrict__ src,
                                             int as, int am, int ao,
                                             int nk, int idx4)
{
    const int mt   = idx4 / (nk * 32);
    const int rem  = idx4 % (nk * 32);
    const int ks   = rem >> 5;
    const int lane = rem & 31;
    const int gid  = lane >> 2, tig = lane & 3;
    const int r0 = mt * 16 + 2 * gid;
    const int r1 = r0 + 1;
    const int k  = ks * 16 + 2 * tig;
    uint4 v;
    v.x = pack2(src[r0 * as + k * am + ao],       src[r0 * as + (k + 1) * am + ao]);
    v.y = pack2(src[r1 * as + k * am + ao],       src[r1 * as + (k + 1) * am + ao]);
    v.z = pack2(src[r0 * as + (k + 8) * am + ao], src[r0 * as + (k + 9) * am + ao]);
    v.w = pack2(src[r1 * as + (k + 8) * am + ao], src[r1 * as + (k + 9) * am + ao]);
    return v;
}

__global__ void prep_kernel(
    const float* __restrict__ dil_w,  const float* __restrict__ cond_w,
    const float* __restrict__ skip_w, const float* __restrict__ res_w,
    const float* __restrict__ p1_w,   const float* __restrict__ p2_w,
    const float* __restrict__ skip_b)
{
    uint4* pk = (uint4*)g_pk;
    const int stride = gridDim.x * blockDim.x;
    const int g0 = blockIdx.x * blockDim.x + threadIdx.x;
    if (g0 < Sn) {
        float s = 0.0f;
        for (int i = 0; i < NBn; i++) s += skip_b[i * Sn + g0];
        g_bs_sum[g0] = s;
    }
    for (int q = g0; q < PK_TOTAL / 4; q += stride) {
        uint4 v;
        if (q < OFF_COND / 4) {
            const int blk = q / (PK_DIL_BLK / 4), r2 = q % (PK_DIL_BLK / 4);
            const int tap = r2 / (PK_DIL_TAP / 4), idx4 = r2 % (PK_DIL_TAP / 4);
            v = pack_frag_h(dil_w + blk * 16384, 128, 2, tap, 4, idx4);
        } else if (q < OFF_SKIP / 4) {
            const int q2 = q - OFF_COND / 4;
            const int blk = q2 / (PK_COND_BLK / 4), idx4 = q2 % (PK_COND_BLK / 4);
            v = pack_frag_h(cond_w + blk * (128 * NMn), NMn, 1, 0, 5, idx4);
        } else if (q < OFF_RES / 4) {
            const int q2 = q - OFF_SKIP / 4;
            const int blk = q2 / (PK_SKIP_BLK / 4), idx4 = q2 % (PK_SKIP_BLK / 4);
            v = pack_frag_h(skip_w + blk * (Sn * Rn), 64, 1, 0, 4, idx4);
        } else if (q < OFF_P1 / 4) {
            const int q2 = q - OFF_RES / 4;
            const int blk = q2 / (PK_RES_BLK / 4), idx4 = q2 % (PK_RES_BLK / 4);
            v = pack_frag_h(res_w + blk * (Rn * Rn), 64, 1, 0, 4, idx4);
        } else if (q < OFF_P2 / 4) {
            v = pack_frag_h(p1_w, 128, 1, 0, 8, q - OFF_P1 / 4);
        } else {
            v = pack_frag_h(p2_w, 256, 1, 0, 16, q - OFF_P2 / 4);
        }
        pk[q] = v;
    }
}

// ---------------------------------------------------------------------------
// cond: transposed conv -> 2 taps; computes channel pairs, stores half2 words
// ---------------------------------------------------------------------------
__global__ __launch_bounds__(256) void cond_kernel(
    const float* __restrict__ mels, const float* __restrict__ mel_w,
    const float* __restrict__ mel_b)
{
    __shared__ float m0s[NMn], m1s[NMn];
    const int b  = blockIdx.y;
    const int t0 = blockIdx.x * 128;
    const int q  = t0 >> 8;
    const int tid = threadIdx.x;
    if (tid < NMn) {
        m0s[tid] = mels[(b * NMn + tid) * 128 + q];
        m1s[tid] = mels[(b * NMn + tid) * 128 + q + 1];
    }
    __syncthreads();
    for (int j = tid; j < (NMn / 2) * 128; j += 256) {
        const int c2 = j >> 7;
        const int tt = j & 127;
        const int t  = t0 + tt;
        const int r  = t & 255;
        const float* w0 = mel_w + (2 * c2) * (NMn * 512);
        const float* w1 = w0 + NMn * 512;
        float a0 = mel_b[2 * c2], a1 = mel_b[2 * c2 + 1];
        #pragma unroll 4
        for (int ci = 0; ci < NMn; ci++) {
            const float mm0 = m0s[ci], mm1 = m1s[ci];
            a0 += w0[ci * 512 + 255 - r] * mm0 + w0[ci * 512 + 511 - r] * mm1;
            a1 += w1[ci * 512 + 255 - r] * mm0 + w1[ci * 512 + 511 - r] * mm1;
        }
        g_condH[(b * (NMn / 2) + c2) * Ln + t] = pack2(a0, a1);
    }
}

__global__ void init_kernel(const float* __restrict__ x,
                            const float* __restrict__ iw,
                            const float* __restrict__ ib)
{
    const int stride = gridDim.x * blockDim.x;
    const int tid0   = blockIdx.x * blockDim.x + threadIdx.x;
    for (int i = tid0; i < Bn * (Rn / 2) * Ln; i += stride) {
        const int t  = i % Ln;
        const int c2 = (i / Ln) % (Rn / 2);
        const int b  = i / (Ln * (Rn / 2));
        const float xv = x[b * Ln + t];
        const float v0 = iw[2 * c2] * xv + ib[2 * c2];
        const float v1 = iw[2 * c2 + 1] * xv + ib[2 * c2 + 1];
        g_res[(b * Rn + 2 * c2) * Ln + t]     = v0;
        g_res[(b * Rn + 2 * c2 + 1) * Ln + t] = v1;
        g_resHA[i] = pack2(v0, v1);
    }
}

// ---------------------------------------------------------------------------
// Block kernel: cp.async staging -> z-GEMM (fp16) -> gate -> h + res update
// smem word rows: 0-31 prev, 32-63 cur, 64-103 cond; h reuses rows 0-31
// ---------------------------------------------------------------------------
constexpr int BLK_SMEM = 104 * AP * 4;   // 56576 B

__global__ __launch_bounds__(256, 2) void block_kernel(
    const float* __restrict__ dil_b, const float* __restrict__ cond_b,
    const float* __restrict__ res_b,
    const float* __restrict__ res_in, float* __restrict__ res_out,
    const unsigned* __restrict__ resH_in, unsigned* __restrict__ resH_out,
    int blk)
{
    extern __shared__ unsigned smu[];
    unsigned* s_act = smu;
    unsigned* s_h   = smu;   // rows 0-31 reused for h words

    const int d = 1 << (blk % 10);
    const float* bd = dil_b  + blk * 128;
    const float* bc = cond_b + blk * 128;
    const float* br = res_b  + blk * Rn;

    const int b   = blockIdx.y;
    const int t0  = blockIdx.x * 128;
    const int tid = threadIdx.x;

    // ---- stage via cp.async (half2 words, pure DMA) ----
    const unsigned* rh = resH_in + b * ((Rn / 2) * Ln);
    for (int i = tid; i < 32 * 32; i += 256) {
        const int row = i >> 5, q = (i & 31) * 4;
        cp16(s_act + (32 + row) * AP + q, rh + row * Ln + t0 + q);
    }
    const unsigned* ch = g_condH + b * ((NMn / 2) * Ln);
    for (int i = tid; i < 40 * 32; i += 256) {
        const int row = i >> 5, q = (i & 31) * 4;
        cp16(s_act + (64 + row) * AP + q, ch + row * Ln + t0 + q);
    }
    if (t0 >= d) {
        const unsigned* rp = rh + t0 - d;
        if ((d & 3) == 0) {
            for (int i = tid; i < 32 * 32; i += 256) {
                const int row = i >> 5, q = (i & 31) * 4;
                cp16(s_act + row * AP + q, rp + row * Ln + q);
            }
        } else if (d == 2) {
            for (int i = tid; i < 32 * 64; i += 256) {
                const int row = i >> 6, q = (i & 63) * 2;
                cp8(s_act + row * AP + q, rp + row * Ln + q);
            }
        } else {
            for (int i = tid; i < 32 * 128; i += 256) {
                const int row = i >> 7, q = i & 127;
                cp4(s_act + row * AP + q, rp + row * Ln + q);
            }
        }
        cp_commit();
        cp_wait0();
    } else {
        cp_commit();
        cp_wait0();
        for (int i = tid; i < 32 * 128; i += 256) {
            const int row = i >> 7, tt = i & 127;
            const int tp = t0 + tt - d;
            s_act[row * AP + tt] = (tp >= 0) ? rh[row * Ln + tp] : 0u;
        }
    }
    __syncthreads();

    const int lane = tid & 31, warp = tid >> 5;
    const int gid = lane >> 2, tig = lane & 3;
    const int mw = warp & 3;
    const int n0 = (warp >> 2) * 64;
    const int m0f = mw * 16;

    // ---- GEMM1: acc[0] = f channels (m0f+2gid, +1), acc[1] = g (+64) ----
    float acc[2][8][4];
    {
        const int cf0 = m0f + 2 * gid, cf1 = cf0 + 1;
        const float f0 = bd[cf0] + bc[cf0],           f1 = bd[cf1] + bc[cf1];
        const float g0 = bd[cf0 + 64] + bc[cf0 + 64], g1 = bd[cf1 + 64] + bc[cf1 + 64];
        #pragma unroll
        for (int j = 0; j < 8; j++) {
            acc[0][j][0] = f0; acc[0][j][1] = f0; acc[0][j][2] = f1; acc[0][j][3] = f1;
            acc[1][j][0] = g0; acc[1][j][1] = g0; acc[1][j][2] = g1; acc[1][j][3] = g1;
        }
    }
    const uint4* pk_dil = (const uint4*)(g_pk + OFF_DIL + blk * PK_DIL_BLK);
    const uint4* pk_c   = (const uint4*)(g_pk + OFF_COND + blk * PK_COND_BLK);
    gemm_h2(acc, s_act, AP,  0, 4, pk_dil + mw * 128,        4 * 128, lane, n0, gid, tig); // tap0*prev
    gemm_h2(acc, s_act, AP, 32, 4, pk_dil + 1024 + mw * 128, 4 * 128, lane, n0, gid, tig); // tap1*cur
    gemm_h2(acc, s_act, AP, 64, 5, pk_c + mw * 160,          4 * 160, lane, n0, gid, tig); // cond

    __syncthreads();

    // ---- gate in registers -> h words, rows 0-31 ----
    {
        const int c2r = (m0f >> 1) + gid;
        #pragma unroll
        for (int j = 0; j < 8; j++) {
            const int t = n0 + j * 8 + tig * 2;
            uint2 w;
            w.x = pack2(gate_fn(acc[0][j][0], acc[1][j][0]),
                        gate_fn(acc[0][j][2], acc[1][j][2]));
            w.y = pack2(gate_fn(acc[0][j][1], acc[1][j][1]),
                        gate_fn(acc[0][j][3], acc[1][j][3]));
            *(uint2*)(s_h + c2r * AP + t) = w;
        }
    }
    __syncthreads();

    // ---- write h to global (coalesced uint4) ----
    {
        unsigned* ho = g_hH + (size_t)(blk * Bn + b) * ((Rn / 2) * Ln) + t0;
        for (int i = tid; i < 32 * 32; i += 256) {
            const int row = i >> 5, q = (i & 31) * 4;
            *(uint4*)(ho + row * Ln + q) = *(const uint4*)(s_h + row * AP + q);
        }
    }

    // ---- GEMM3: res_out = res_in + Wr*h + br ----
    float accr[8][4];
    const int mr = mw * 16;
    {
        const int r0 = mr + 2 * gid, r1 = r0 + 1;
        const float z0 = br[r0], z1 = br[r1];
        #pragma unroll
        for (int j = 0; j < 8; j++) {
            accr[j][0] = z0; accr[j][1] = z0;
            accr[j][2] = z1; accr[j][3] = z1;
        }
    }
    const uint4* pk_r = (const uint4*)(g_pk + OFF_RES + blk * PK_RES_BLK);
    gemm_h1(accr, s_h, AP, 0, 4, pk_r + (mr >> 4) * 128, lane, n0, gid, tig);

    {
        const float* rib = res_in  + b * (Rn * Ln) + t0;
        float*       rob = res_out + b * (Rn * Ln) + t0;
        unsigned*    rhb = resH_out + b * ((Rn / 2) * Ln) + t0;
        const int r0 = mr + 2 * gid, r1 = r0 + 1;
        const int rw = (mr >> 1) + gid;
        #pragma unroll
        for (int j = 0; j < 8; j++) {
            const int c = n0 + j * 8 + tig * 2;
            float v00 = rib[r0 * Ln + c]     + accr[j][0];
            float v01 = rib[r0 * Ln + c + 1] + accr[j][1];
            float v10 = rib[r1 * Ln + c]     + accr[j][2];
            float v11 = rib[r1 * Ln + c + 1] + accr[j][3];
            float2 w0; w0.x = v00; w0.y = v01;
            float2 w1; w1.x = v10; w1.y = v11;
            *(float2*)(rob + r0 * Ln + c) = w0;
            *(float2*)(rob + r1 * Ln + c) = w1;
            uint2 hw; hw.x = pack2(v00, v10); hw.y = pack2(v01, v11);
            *(uint2*)(rhb + rw * Ln + c) = hw;
        }
    }
}

// ---------------------------------------------------------------------------
// Tail kernel: skip = bias_sum + sum_i Ws_i h_i -> relu -> p1 -> relu -> p2
// smem: rows 0-63 = h double buffer (2x32) then relu(skip) words [64][AP];
//       rows 64-191 = relu(y1) words [128][AP]
// ---------------------------------------------------------------------------
constexpr int SP_SMEM = (64 + 128) * AP * 4;   // 104448 B

__global__ __launch_bounds__(256, 2) void sp_kernel(
    const float* __restrict__ b1, const float* __restrict__ b2,
    float* __restrict__ out)
{
    extern __shared__ unsigned smu[];
    unsigned* s_hb = smu;                // 2 buffers of [32][AP]
    unsigned* s_sk = smu;                // reuse: relu(skip) words [64][AP]
    unsigned* s_y1 = smu + 64 * AP;      // relu(y1) words [128][AP]

    const int b   = blockIdx.y;
    const int t0  = blockIdx.x * 128;
    const int tid = threadIdx.x;
    const int lane = tid & 31, warp = tid >> 5;
    const int gid = lane >> 2, tig = lane & 3;
    const int mw = warp & 3;
    const int n0 = (warp >> 2) * 64;

    // ---- Phase A: skip accumulation over 30 layers ----
    const int m0s = mw * 32;
    float acc[2][8][4];
    {
        const int c00 = m0s + 2 * gid;
        const float z0 = g_bs_sum[c00],      z1 = g_bs_sum[c00 + 1];
        const float z2 = g_bs_sum[c00 + 16], z3 = g_bs_sum[c00 + 17];
        #pragma unroll
        for (int j = 0; j < 8; j++) {
            acc[0][j][0] = z0; acc[0][j][1] = z0; acc[0][j][2] = z1; acc[0][j][3] = z1;
            acc[1][j][0] = z2; acc[1][j][1] = z2; acc[1][j][2] = z3; acc[1][j][3] = z3;
        }
    }
    {
        const unsigned* hp = g_hH + (size_t)(0 * Bn + b) * ((Rn / 2) * Ln) + t0;
        for (int i = tid; i < 32 * 32; i += 256) {
            const int row = i >> 5, q = (i & 31) * 4;
            cp16(s_hb + row * AP + q, hp + row * Ln + q);
        }
        cp_commit();
        cp_wait0();
    }
    __syncthreads();

    const uint4* pk_s0 = (const uint4*)(g_pk + OFF_SKIP) + (m0s >> 4) * 128;
    for (int i = 0; i < NBn; i++) {
        if (i + 1 < NBn) {
            const unsigned* hp = g_hH + (size_t)((i + 1) * Bn + b) * ((Rn / 2) * Ln) + t0;
            unsigned* dst = s_hb + ((i + 1) & 1) * (32 * AP);
            for (int k = tid; k < 32 * 32; k += 256) {
                const int row = k >> 5, q = (k & 31) * 4;
                cp16(dst + row * AP + q, hp + row * Ln + q);
            }
            cp_commit();
        }
        gemm_h2(acc, s_hb + (i & 1) * (32 * AP), AP, 0, 4,
                pk_s0 + i * (PK_SKIP_BLK / 4), 128, lane, n0, gid, tig);
        cp_wait0();
        __syncthreads();
    }

    // ---- Phase B: relu(skip) -> half2 words [64][AP] ----
    #pragma unroll
    for (int mi = 0; mi < 2; mi++) {
        const int c2 = (m0s >> 1) + mi * 8 + gid;
        #pragma unroll
        for (int j = 0; j < 8; j++) {
            const int t = n0 + j * 8 + tig * 2;
            uint2 w;
            w.x = pack2(fmaxf(acc[mi][j][0], 0.0f), fmaxf(acc[mi][j][2], 0.0f));
            w.y = pack2(fmaxf(acc[mi][j][1], 0.0f), fmaxf(acc[mi][j][3], 0.0f));
            *(uint2*)(s_sk + c2 * AP + t) = w;
        }
    }
    __syncthreads();

    // ---- Phase C: p1 (M=256, K=128), both 64-col halves -> relu -> s_y1 ----
    const int m0p = warp * 32;
    const uint4* pkP1 = (const uint4*)(g_pk + OFF_P1) + (m0p >> 4) * 256;
    #pragma unroll
    for (int nh = 0; nh < 2; nh++) {
        const int nn = nh * 64;
        {
            const int c00 = m0p + 2 * gid;
            const float z0 = b1[c00],      z1 = b1[c00 + 1];
            const float z2 = b1[c00 + 16], z3 = b1[c00 + 17];
            #pragma unroll
            for (int j = 0; j < 8; j++) {
                acc[0][j][0] = z0; acc[0][j][1] = z0; acc[0][j][2] = z1; acc[0][j][3] = z1;
                acc[1][j][0] = z2; acc[1][j][1] = z2; acc[1][j][2] = z3; acc[1][j][3] = z3;
            }
        }
        gemm_h2(acc, s_sk, AP, 0, 8, pkP1, 256, lane, nn, gid, tig);
        #pragma unroll
        for (int mi = 0; mi < 2; mi++) {
            const int c2 = (m0p >> 1) + mi * 8 + gid;
            #pragma unroll
            for (int j = 0; j < 8; j++) {
                const int t = nn + j * 8 + tig * 2;
                uint2 w;
                w.x = pack2(fmaxf(acc[mi][j][0], 0.0f), fmaxf(acc[mi][j][2], 0.0f));
                w.y = pack2(fmaxf(acc[mi][j][1], 0.0f), fmaxf(acc[mi][j][3], 0.0f));
                *(uint2*)(s_y1 + c2 * AP + t) = w;
            }
        }
    }
    __syncthreads();

    // ---- Phase D: p2 (M=256, K=256), both 64-col halves -> out (fp32) ----
    const uint4* pkP2 = (const uint4*)(g_pk + OFF_P2) + (m0p >> 4) * 512;
    float* ob = out + (size_t)b * (NCn * Ln) + t0;
    #pragma unroll
    for (int nh = 0; nh < 2; nh++) {
        const int nn = nh * 64;
        {
            const int c00 = m0p + 2 * gid;
            const float z0 = b2[c00],      z1 = b2[c00 + 1];
            const float z2 = b2[c00 + 16], z3 = b2[c00 + 17];
            #pragma unroll
            for (int j = 0; j < 8; j++) {
                acc[0][j][0] = z0; acc[0][j][1] = z0; acc[0][j][2] = z1; acc[0][j][3] = z1;
                acc[1][j][0] = z2; acc[1][j][1] = z2; acc[1][j][2] = z3; acc[1][j][3] = z3;
            }
        }
        gemm_h2(acc, s_y1, AP, 0, 16, pkP2, 512, lane, nn, gid, tig);
        #pragma unroll
        for (int mi = 0; mi < 2; mi++) {
            const int co0 = m0p + mi * 16 + 2 * gid;
            const int co1 = co0 + 1;
            #pragma unroll
            for (int j = 0; j < 8; j++) {
                const int c = nn + j * 8 + tig * 2;
                float2 w0; w0.x = acc[mi][j][0]; w0.y = acc[mi][j][1];
                float2 w1; w1.x = acc[mi][j][2]; w1.y = acc[mi][j][3];
                *(float2*)(ob + co0 * Ln + c) = w0;
                *(float2*)(ob + co1 * Ln + c) = w1;
            }
        }
    }
}

} // anonymous namespace

// ---------------------------------------------------------------------------
extern "C" void kernel_launch(void* const* d_in, const int* in_sizes, int n_in,
                              void* d_out, int out_size)
{
    (void)in_sizes; (void)n_in; (void)out_size;
    const float* x          = (const float*)d_in[0];
    const float* mels       = (const float*)d_in[1];
    const float* input_w    = (const float*)d_in[2];
    const float* input_b    = (const float*)d_in[3];
    const float* mel_w      = (const float*)d_in[4];
    const float* mel_b      = (const float*)d_in[5];
    const float* blk_dil_w  = (const float*)d_in[6];
    const float* blk_dil_b  = (const float*)d_in[7];
    const float* blk_cond_w = (const float*)d_in[8];
    const float* blk_cond_b = (const float*)d_in[9];
    const float* blk_skip_w = (const float*)d_in[10];
    const float* blk_skip_b = (const float*)d_in[11];
    const float* blk_res_w  = (const float*)d_in[12];
    const float* blk_res_b  = (const float*)d_in[13];
    const float* post1_w    = (const float*)d_in[14];
    const float* post1_b    = (const float*)d_in[15];
    const float* post2_w    = (const float*)d_in[16];
    const float* post2_b    = (const float*)d_in[17];

    cudaFuncSetAttribute(block_kernel, cudaFuncAttributeMaxDynamicSharedMemorySize, BLK_SMEM);
    cudaFuncSetAttribute(sp_kernel,    cudaFuncAttributeMaxDynamicSharedMemorySize, SP_SMEM);

    float* resA; cudaGetSymbolAddress((void**)&resA, g_res);
    float* resB; cudaGetSymbolAddress((void**)&resB, g_resB);
    unsigned* rhA; cudaGetSymbolAddress((void**)&rhA, g_resHA);
    unsigned* rhB; cudaGetSymbolAddress((void**)&rhB, g_resHB);

    prep_kernel<<<1024, 256>>>(blk_dil_w, blk_cond_w, blk_skip_w, blk_res_w,
                               post1_w, post2_w, blk_skip_b);
    cond_kernel<<<dim3(Ln / 128, Bn), 256>>>(mels, mel_w, mel_b);
    init_kernel<<<512, 256>>>(x, input_w, input_b);

    for (int i = 0; i < NBn; i++) {
        const float*    rin  = (i & 1) ? resB : resA;
        float*          rout = (i & 1) ? resA : resB;
        const unsigned* hin  = (i & 1) ? rhB : rhA;
        unsigned*       hout = (i & 1) ? rhA : rhB;
        block_kernel<<<dim3(Ln / 128, Bn), 256, BLK_SMEM>>>(
            blk_dil_b, blk_cond_b, blk_res_b, rin, rout, hin, hout, i);
    }

    sp_kernel<<<dim3(Ln / 128, Bn), 256, SP_SMEM>>>(post1_b, post2_b, (float*)d_out);
}

// round 12
// speedup vs baseline: 1.4363x; 1.0039x over previous
#include <cuda_runtime.h>
#include <cuda_fp16.h>

// ---------------------------------------------------------------------------
// WaveNet Mel2Raw — fp16 mma.m16n8k16 (fp32 accum), deferred skip,
// ONE persistent block kernel with per-tile dependency flags (pipelined
// layers), per-layer res slices (no WAR), L2-scope res reads (.cg).
// ---------------------------------------------------------------------------

namespace {

constexpr int Bn  = 2;
constexpr int Ln  = 32512;
constexpr int Rn  = 64;
constexpr int Sn  = 128;
constexpr int NMn = 80;
constexpr int NCn = 256;
constexpr int NBn = 30;

constexpr int AP = 136;   // smem pitch in 32-bit words
constexpr int NT = 254;   // time tiles per batch
constexpr int TASKS_PER_LAYER = Bn * NT;        // 508
constexpr int TOTAL_TASKS = NBn * TASKS_PER_LAYER;

// ---- packed fp16 weight buffer (A fragments, 32-bit words) ----
constexpr int PK_DIL_BLK  = 8192;
constexpr int PK_DIL_TAP  = 4096;
constexpr int OFF_DIL     = 0;
constexpr int PK_COND_BLK = 5120;
constexpr int OFF_COND    = 245760;
constexpr int PK_SKIP_BLK = 4096;
constexpr int OFF_SKIP    = 399360;
constexpr int PK_RES_BLK  = 2048;
constexpr int OFF_RES     = 522240;
constexpr int OFF_P1      = 583680;
constexpr int OFF_P2      = 600064;
constexpr int PK_TOTAL    = 632832;

constexpr size_t RES_SLICE  = (size_t)Bn * Rn * Ln;        // fp32 words
constexpr size_t RESH_SLICE = (size_t)Bn * (Rn / 2) * Ln;  // half2 words

__device__ unsigned g_pk[PK_TOTAL];
__device__ float    g_bs_sum[Sn];

__device__ unsigned g_condH[Bn * (NMn/2) * Ln];
__device__ float    g_resF [(NBn + 1) * RES_SLICE];    // per-layer fp32 res
__device__ unsigned g_resHs[(NBn + 1) * RESH_SLICE];   // per-layer half2 res
__device__ unsigned g_hH   [NBn * Bn * (Rn/2) * Ln];   // gate outputs
__device__ int      g_flag [TOTAL_TASKS];              // RAW flags

__device__ __forceinline__ float ex2f(float x) {
    float y; asm("ex2.approx.f32 %0, %1;" : "=f"(y) : "f"(x)); return y;
}
__device__ __forceinline__ float rcpf(float x) {
    float y; asm("rcp.approx.f32 %0, %1;" : "=f"(y) : "f"(x)); return y;
}
__device__ __forceinline__ float gate_fn(float f, float g) {
    float ef = ex2f(2.8853900817779268f * f);
    float th = 1.0f - 2.0f * rcpf(ef + 1.0f);
    float sg = rcpf(1.0f + ex2f(-1.4426950408889634f * g));
    return th * sg;
}
__device__ __forceinline__ unsigned pack2(float a, float b) {
    __half2 h = __floats2half2_rn(a, b);
    return *(unsigned*)&h;
}

__device__ __forceinline__ void cp16(unsigned* s, const unsigned* g) {
    unsigned sa = (unsigned)__cvta_generic_to_shared(s);
    asm volatile("cp.async.ca.shared.global [%0], [%1], 16;" :: "r"(sa), "l"(g));
}
__device__ __forceinline__ void cp16cg(unsigned* s, const unsigned* g) {
    unsigned sa = (unsigned)__cvta_generic_to_shared(s);
    asm volatile("cp.async.cg.shared.global [%0], [%1], 16;" :: "r"(sa), "l"(g));
}
__device__ __forceinline__ void cp_commit() { asm volatile("cp.async.commit_group;"); }
__device__ __forceinline__ void cp_wait0()  { asm volatile("cp.async.wait_group 0;"); }

__device__ __forceinline__ void mmah(float c[4], const unsigned a[4], const unsigned b[2]) {
    asm volatile(
        "mma.sync.aligned.m16n8k16.row.col.f32.f16.f16.f32 "
        "{%0,%1,%2,%3},{%4,%5,%6,%7},{%8,%9},{%0,%1,%2,%3};"
        : "+f"(c[0]), "+f"(c[1]), "+f"(c[2]), "+f"(c[3])
        : "r"(a[0]), "r"(a[1]), "r"(a[2]), "r"(a[3]), "r"(b[0]), "r"(b[1]));
}

__device__ __forceinline__ void gemm_h2(
    float acc[2][8][4], const unsigned* __restrict__ sB, int pitch,
    int rb, int nk, const uint4* __restrict__ pkA, int miStride,
    int lane, int n0, int gid, int tig)
{
    #pragma unroll
    for (int ks = 0; ks < nk; ks++) {
        uint4 va0 = pkA[ks * 32 + lane];
        uint4 va1 = pkA[miStride + ks * 32 + lane];
        unsigned A0[4] = {va0.x, va0.y, va0.z, va0.w};
        unsigned A1[4] = {va1.x, va1.y, va1.z, va1.w};
        const unsigned* b0 = sB + (rb + ks * 8 + tig) * pitch + n0 + gid;
        const unsigned* b1 = b0 + 4 * pitch;
        #pragma unroll
        for (int j = 0; j < 8; j++) {
            unsigned bf[2] = { b0[j * 8], b1[j * 8] };
            mmah(acc[0][j], A0, bf);
            mmah(acc[1][j], A1, bf);
        }
    }
}

__device__ __forceinline__ void gemm_h1(
    float acc[8][4], const unsigned* __restrict__ sB, int pitch,
    int rb, int nk, const uint4* __restrict__ pkA,
    int lane, int n0, int gid, int tig)
{
    #pragma unroll
    for (int ks = 0; ks < nk; ks++) {
        uint4 va = pkA[ks * 32 + lane];
        unsigned A[4] = {va.x, va.y, va.z, va.w};
        const unsigned* b0 = sB + (rb + ks * 8 + tig) * pitch + n0 + gid;
        const unsigned* b1 = b0 + 4 * pitch;
        #pragma unroll
        for (int j = 0; j < 8; j++) {
            unsigned bf[2] = { b0[j * 8], b1[j * 8] };
            mmah(acc[j], A, bf);
        }
    }
}

// ---------------------------------------------------------------------------
// prep: pack weights into fp16 A fragments (row perm phi) + skip-bias sum
// ---------------------------------------------------------------------------
__device__ __forceinline__ uint4 pack_frag_h(const float* __restrict__ src,
                                             int as, int am, int ao,
                                             int nk, int idx4)
{
    const int mt   = idx4 / (nk * 32);
    const int rem  = idx4 % (nk * 32);
    const int ks   = rem >> 5;
    const int lane = rem & 31;
    const int gid  = lane >> 2, tig = lane & 3;
    const int r0 = mt * 16 + 2 * gid;
    const int r1 = r0 + 1;
    const int k  = ks * 16 + 2 * tig;
    uint4 v;
    v.x = pack2(src[r0 * as + k * am + ao],       src[r0 * as + (k + 1) * am + ao]);
    v.y = pack2(src[r1 * as + k * am + ao],       src[r1 * as + (k + 1) * am + ao]);
    v.z = pack2(src[r0 * as + (k + 8) * am + ao], src[r0 * as + (k + 9) * am + ao]);
    v.w = pack2(src[r1 * as + (k + 8) * am + ao], src[r1 * as + (k + 9) * am + ao]);
    return v;
}

__global__ void prep_kernel(
    const float* __restrict__ dil_w,  const float* __restrict__ cond_w,
    const float* __restrict__ skip_w, const float* __restrict__ res_w,
    const float* __restrict__ p1_w,   const float* __restrict__ p2_w,
    const float* __restrict__ skip_b)
{
    uint4* pk = (uint4*)g_pk;
    const int stride = gridDim.x * blockDim.x;
    const int g0 = blockIdx.x * blockDim.x + threadIdx.x;
    if (g0 < Sn) {
        float s = 0.0f;
        for (int i = 0; i < NBn; i++) s += skip_b[i * Sn + g0];
        g_bs_sum[g0] = s;
    }
    for (int q = g0; q < PK_TOTAL / 4; q += stride) {
        uint4 v;
        if (q < OFF_COND / 4) {
            const int blk = q / (PK_DIL_BLK / 4), r2 = q % (PK_DIL_BLK / 4);
            const int tap = r2 / (PK_DIL_TAP / 4), idx4 = r2 % (PK_DIL_TAP / 4);
            v = pack_frag_h(dil_w + blk * 16384, 128, 2, tap, 4, idx4);
        } else if (q < OFF_SKIP / 4) {
            const int q2 = q - OFF_COND / 4;
            const int blk = q2 / (PK_COND_BLK / 4), idx4 = q2 % (PK_COND_BLK / 4);
            v = pack_frag_h(cond_w + blk * (128 * NMn), NMn, 1, 0, 5, idx4);
        } else if (q < OFF_RES / 4) {
            const int q2 = q - OFF_SKIP / 4;
            const int blk = q2 / (PK_SKIP_BLK / 4), idx4 = q2 % (PK_SKIP_BLK / 4);
            v = pack_frag_h(skip_w + blk * (Sn * Rn), 64, 1, 0, 4, idx4);
        } else if (q < OFF_P1 / 4) {
            const int q2 = q - OFF_RES / 4;
            const int blk = q2 / (PK_RES_BLK / 4), idx4 = q2 % (PK_RES_BLK / 4);
            v = pack_frag_h(res_w + blk * (Rn * Rn), 64, 1, 0, 4, idx4);
        } else if (q < OFF_P2 / 4) {
            v = pack_frag_h(p1_w, 128, 1, 0, 8, q - OFF_P1 / 4);
        } else {
            v = pack_frag_h(p2_w, 256, 1, 0, 16, q - OFF_P2 / 4);
        }
        pk[q] = v;
    }
}

// ---------------------------------------------------------------------------
__global__ __launch_bounds__(256) void cond_kernel(
    const float* __restrict__ mels, const float* __restrict__ mel_w,
    const float* __restrict__ mel_b)
{
    __shared__ float m0s[NMn], m1s[NMn];
    const int b  = blockIdx.y;
    const int t0 = blockIdx.x * 128;
    const int q  = t0 >> 8;
    const int tid = threadIdx.x;
    if (tid < NMn) {
        m0s[tid] = mels[(b * NMn + tid) * 128 + q];
        m1s[tid] = mels[(b * NMn + tid) * 128 + q + 1];
    }
    __syncthreads();
    for (int j = tid; j < (NMn / 2) * 128; j += 256) {
        const int c2 = j >> 7;
        const int tt = j & 127;
        const int t  = t0 + tt;
        const int r  = t & 255;
        const float* w0 = mel_w + (2 * c2) * (NMn * 512);
        const float* w1 = w0 + NMn * 512;
        float a0 = mel_b[2 * c2], a1 = mel_b[2 * c2 + 1];
        #pragma unroll 4
        for (int ci = 0; ci < NMn; ci++) {
            const float mm0 = m0s[ci], mm1 = m1s[ci];
            a0 += w0[ci * 512 + 255 - r] * mm0 + w0[ci * 512 + 511 - r] * mm1;
            a1 += w1[ci * 512 + 255 - r] * mm0 + w1[ci * 512 + 511 - r] * mm1;
        }
        g_condH[(b * (NMn / 2) + c2) * Ln + t] = pack2(a0, a1);
    }
}

__global__ void init_kernel(const float* __restrict__ x,
                            const float* __restrict__ iw,
                            const float* __restrict__ ib)
{
    const int stride = gridDim.x * blockDim.x;
    const int tid0   = blockIdx.x * blockDim.x + threadIdx.x;
    for (int i = tid0; i < Bn * (Rn / 2) * Ln; i += stride) {
        const int t  = i % Ln;
        const int c2 = (i / Ln) % (Rn / 2);
        const int b  = i / (Ln * (Rn / 2));
        const float xv = x[b * Ln + t];
        const float v0 = iw[2 * c2] * xv + ib[2 * c2];
        const float v1 = iw[2 * c2 + 1] * xv + ib[2 * c2 + 1];
        g_resF[(size_t)(b * Rn + 2 * c2) * Ln + t]     = v0;
        g_resF[(size_t)(b * Rn + 2 * c2 + 1) * Ln + t] = v1;
        g_resHs[i] = pack2(v0, v1);
    }
    for (int i = tid0; i < TOTAL_TASKS; i += stride) g_flag[i] = 0;
}

// ---------------------------------------------------------------------------
// Persistent block kernel: all 30 layers pipelined via per-tile flags.
// Each task = (layer l, batch b, time tile kt). Task body == round-10
// block_kernel. Res reads are L2-scope (.cg) — no L1 staleness.
// ---------------------------------------------------------------------------
constexpr int BLK_SMEM = 104 * AP * 4;   // 56576 B -> 2 CTAs/SM

__global__ __launch_bounds__(256, 2) void persist_kernel(
    const float* __restrict__ dil_b, const float* __restrict__ cond_b,
    const float* __restrict__ res_b)
{
    extern __shared__ unsigned smu[];
    unsigned* s_act = smu;
    unsigned* s_h   = smu;   // rows 0-31 reused for h words

    const int tid  = threadIdx.x;
    const int lane = tid & 31, warp = tid >> 5;
    const int gid  = lane >> 2, tig = lane & 3;
    const int mw   = warp & 3;
    const int n0   = (warp >> 2) * 64;
    const int m0f  = mw * 16;

    for (int T = blockIdx.x; T < TOTAL_TASKS; T += gridDim.x) {
        const int l  = T / TASKS_PER_LAYER;
        const int j  = T % TASKS_PER_LAYER;
        const int b  = j / NT;
        const int kt = j % NT;
        const int t0 = kt * 128;
        const int d  = 1 << (l % 10);

        const float* bd = dil_b  + l * 128;
        const float* bc = cond_b + l * 128;
        const float* br = res_b  + l * Rn;

        const float*    res_in  = g_resF  + (size_t)l * RES_SLICE  + (size_t)b * (Rn * Ln);
        float*          res_out = g_resF  + (size_t)(l + 1) * RES_SLICE  + (size_t)b * (Rn * Ln);
        const unsigned* rh      = g_resHs + (size_t)l * RESH_SLICE + (size_t)b * ((Rn / 2) * Ln);
        unsigned*       rh_out  = g_resHs + (size_t)(l + 1) * RESH_SLICE + (size_t)b * ((Rn / 2) * Ln);

        // ---- wait for producer tiles of layer l-1 (RAW) ----
        if (l > 0) {
            if (tid == 0) {
                const int base = (l - 1) * TASKS_PER_LAYER + b * NT;
                int k0 = kt - 4; if (k0 < 0) k0 = 0;
                for (int k = kt; k >= k0; k--) {
                    while (atomicAdd(&g_flag[base + k], 0) == 0) __nanosleep(64);
                }
                __threadfence();
            }
            __syncthreads();
        }

        // ---- stage activations (res via .cg; cond via .ca) ----
        for (int i = tid; i < 32 * 32; i += 256) {
            const int row = i >> 5, q = (i & 31) * 4;
            cp16cg(s_act + (32 + row) * AP + q, rh + row * Ln + t0 + q);
        }
        const unsigned* ch = g_condH + b * ((NMn / 2) * Ln);
        for (int i = tid; i < 40 * 32; i += 256) {
            const int row = i >> 5, q = (i & 31) * 4;
            cp16(s_act + (64 + row) * AP + q, ch + row * Ln + t0 + q);
        }
        if (t0 >= d) {
            const unsigned* rp = rh + t0 - d;
            if ((d & 3) == 0) {
                for (int i = tid; i < 32 * 32; i += 256) {
                    const int row = i >> 5, q = (i & 31) * 4;
                    cp16cg(s_act + row * AP + q, rp + row * Ln + q);
                }
            } else if (d == 2) {
                for (int i = tid; i < 32 * 64; i += 256) {
                    const int row = i >> 6, q = (i & 63) * 2;
                    uint2 v = __ldcg((const uint2*)(rp + row * Ln + q));
                    *(uint2*)(s_act + row * AP + q) = v;
                }
            } else {
                for (int i = tid; i < 32 * 128; i += 256) {
                    const int row = i >> 7, q = i & 127;
                    s_act[row * AP + q] = __ldcg(rp + row * Ln + q);
                }
            }
        } else {
            for (int i = tid; i < 32 * 128; i += 256) {
                const int row = i >> 7, tt = i & 127;
                const int tp = t0 + tt - d;
                s_act[row * AP + tt] = (tp >= 0) ? __ldcg(rh + row * Ln + tp) : 0u;
            }
        }
        cp_commit();
        cp_wait0();
        __syncthreads();

        // ---- GEMM1: acc[0] = f channels, acc[1] = g channels ----
        float acc[2][8][4];
        {
            const int cf0 = m0f + 2 * gid, cf1 = cf0 + 1;
            const float f0 = bd[cf0] + bc[cf0],           f1 = bd[cf1] + bc[cf1];
            const float g0 = bd[cf0 + 64] + bc[cf0 + 64], g1 = bd[cf1 + 64] + bc[cf1 + 64];
            #pragma unroll
            for (int jj = 0; jj < 8; jj++) {
                acc[0][jj][0] = f0; acc[0][jj][1] = f0; acc[0][jj][2] = f1; acc[0][jj][3] = f1;
                acc[1][jj][0] = g0; acc[1][jj][1] = g0; acc[1][jj][2] = g1; acc[1][jj][3] = g1;
            }
        }
        const uint4* pk_dil = (const uint4*)(g_pk + OFF_DIL + l * PK_DIL_BLK);
        const uint4* pk_c   = (const uint4*)(g_pk + OFF_COND + l * PK_COND_BLK);
        gemm_h2(acc, s_act, AP,  0, 4, pk_dil + mw * 128,        4 * 128, lane, n0, gid, tig);
        gemm_h2(acc, s_act, AP, 32, 4, pk_dil + 1024 + mw * 128, 4 * 128, lane, n0, gid, tig);
        gemm_h2(acc, s_act, AP, 64, 5, pk_c + mw * 160,          4 * 160, lane, n0, gid, tig);

        __syncthreads();

        // ---- gate in registers -> h words, rows 0-31 ----
        {
            const int c2r = (m0f >> 1) + gid;
            #pragma unroll
            for (int jj = 0; jj < 8; jj++) {
                const int t = n0 + jj * 8 + tig * 2;
                uint2 w;
                w.x = pack2(gate_fn(acc[0][jj][0], acc[1][jj][0]),
                            gate_fn(acc[0][jj][2], acc[1][jj][2]));
                w.y = pack2(gate_fn(acc[0][jj][1], acc[1][jj][1]),
                            gate_fn(acc[0][jj][3], acc[1][jj][3]));
                *(uint2*)(s_h + c2r * AP + t) = w;
            }
        }
        __syncthreads();

        // ---- write h to global (coalesced uint4) ----
        {
            unsigned* ho = g_hH + (size_t)(l * Bn + b) * ((Rn / 2) * Ln) + t0;
            for (int i = tid; i < 32 * 32; i += 256) {
                const int row = i >> 5, q = (i & 31) * 4;
                *(uint4*)(ho + row * Ln + q) = *(const uint4*)(s_h + row * AP + q);
            }
        }

        // ---- GEMM3: res_out = res_in + Wr*h + br ----
        float accr[8][4];
        const int mr = mw * 16;
        {
            const int r0 = mr + 2 * gid, r1 = r0 + 1;
            const float z0 = br[r0], z1 = br[r1];
            #pragma unroll
            for (int jj = 0; jj < 8; jj++) {
                accr[jj][0] = z0; accr[jj][1] = z0;
                accr[jj][2] = z1; accr[jj][3] = z1;
            }
        }
        const uint4* pk_r = (const uint4*)(g_pk + OFF_RES + l * PK_RES_BLK);
        gemm_h1(accr, s_h, AP, 0, 4, pk_r + (mr >> 4) * 128, lane, n0, gid, tig);

        {
            const float* rib = res_in  + t0;
            float*       rob = res_out + t0;
            unsigned*    rhb = rh_out + t0;
            const int r0 = mr + 2 * gid, r1 = r0 + 1;
            const int rw = (mr >> 1) + gid;
            #pragma unroll
            for (int jj = 0; jj < 8; jj++) {
                const int c = n0 + jj * 8 + tig * 2;
                float2 i0 = __ldcg((const float2*)(rib + r0 * Ln + c));
                float2 i1 = __ldcg((const float2*)(rib + r1 * Ln + c));
                float v00 = i0.x + accr[jj][0];
                float v01 = i0.y + accr[jj][1];
                float v10 = i1.x + accr[jj][2];
                float v11 = i1.y + accr[jj][3];
                float2 w0; w0.x = v00; w0.y = v01;
                float2 w1; w1.x = v10; w1.y = v11;
                *(float2*)(rob + r0 * Ln + c) = w0;
                *(float2*)(rob + r1 * Ln + c) = w1;
                uint2 hw; hw.x = pack2(v00, v10); hw.y = pack2(v01, v11);
                *(uint2*)(rhb + rw * Ln + c) = hw;
            }
        }

        // ---- publish this tile (release) ----
        __threadfence();
        __syncthreads();
        if (tid == 0) atomicExch(&g_flag[T], 1);
    }
}

// ---------------------------------------------------------------------------
// Tail: skip = bias_sum + sum_i Ws_i h_i -> relu -> p1 -> relu -> p2
// ---------------------------------------------------------------------------
constexpr int SP_SMEM = (64 + 128) * AP * 4;   // 104448 B

__global__ __launch_bounds__(256, 2) void sp_kernel(
    const float* __restrict__ b1, const float* __restrict__ b2,
    float* __restrict__ out)
{
    extern __shared__ unsigned smu[];
    unsigned* s_hb = smu;
    unsigned* s_sk = smu;
    unsigned* s_y1 = smu + 64 * AP;

    const int b   = blockIdx.y;
    const int t0  = blockIdx.x * 128;
    const int tid = threadIdx.x;
    const int lane = tid & 31, warp = tid >> 5;
    const int gid = lane >> 2, tig = lane & 3;
    const int mw = warp & 3;
    const int n0 = (warp >> 2) * 64;
    const int m0s = mw * 32;

    float acc[2][8][4];
    {
        const int c00 = m0s + 2 * gid;
        const float z0 = g_bs_sum[c00],      z1 = g_bs_sum[c00 + 1];
        const float z2 = g_bs_sum[c00 + 16], z3 = g_bs_sum[c00 + 17];
        #pragma unroll
        for (int j = 0; j < 8; j++) {
            acc[0][j][0] = z0; acc[0][j][1] = z0; acc[0][j][2] = z1; acc[0][j][3] = z1;
            acc[1][j][0] = z2; acc[1][j][1] = z2; acc[1][j][2] = z3; acc[1][j][3] = z3;
        }
    }
    {
        const unsigned* hp = g_hH + (size_t)(0 * Bn + b) * ((Rn / 2) * Ln) + t0;
        for (int i = tid; i < 32 * 32; i += 256) {
            const int row = i >> 5, q = (i & 31) * 4;
            cp16(s_hb + row * AP + q, hp + row * Ln + q);
        }
        cp_commit();
        cp_wait0();
    }
    __syncthreads();

    const uint4* pk_s0 = (const uint4*)(g_pk + OFF_SKIP) + (m0s >> 4) * 128;
    for (int i = 0; i < NBn; i++) {
        if (i + 1 < NBn) {
            const unsigned* hp = g_hH + (size_t)((i + 1) * Bn + b) * ((Rn / 2) * Ln) + t0;
            unsigned* dst = s_hb + ((i + 1) & 1) * (32 * AP);
            for (int k = tid; k < 32 * 32; k += 256) {
                const int row = k >> 5, q = (k & 31) * 4;
                cp16(dst + row * AP + q, hp + row * Ln + q);
            }
            cp_commit();
        }
        gemm_h2(acc, s_hb + (i & 1) * (32 * AP), AP, 0, 4,
                pk_s0 + i * (PK_SKIP_BLK / 4), 128, lane, n0, gid, tig);
        cp_wait0();
        __syncthreads();
    }

    // relu(skip) -> half2 words [64][AP]
    #pragma unroll
    for (int mi = 0; mi < 2; mi++) {
        const int c2 = (m0s >> 1) + mi * 8 + gid;
        #pragma unroll
        for (int j = 0; j < 8; j++) {
            const int t = n0 + j * 8 + tig * 2;
            uint2 w;
            w.x = pack2(fmaxf(acc[mi][j][0], 0.0f), fmaxf(acc[mi][j][2], 0.0f));
            w.y = pack2(fmaxf(acc[mi][j][1], 0.0f), fmaxf(acc[mi][j][3], 0.0f));
            *(uint2*)(s_sk + c2 * AP + t) = w;
        }
    }
    __syncthreads();

    // p1 (M=256, K=128), both halves -> relu -> s_y1
    const int m0p = warp * 32;
    const uint4* pkP1 = (const uint4*)(g_pk + OFF_P1) + (m0p >> 4) * 256;
    #pragma unroll
    for (int nh = 0; nh < 2; nh++) {
        const int nn = nh * 64;
        {
            const int c00 = m0p + 2 * gid;
            const float z0 = b1[c00],      z1 = b1[c00 + 1];
            const float z2 = b1[c00 + 16], z3 = b1[c00 + 17];
            #pragma unroll
            for (int j = 0; j < 8; j++) {
                acc[0][j][0] = z0; acc[0][j][1] = z0; acc[0][j][2] = z1; acc[0][j][3] = z1;
                acc[1][j][0] = z2; acc[1][j][1] = z2; acc[1][j][2] = z3; acc[1][j][3] = z3;
            }
        }
        gemm_h2(acc, s_sk, AP, 0, 8, pkP1, 256, lane, nn, gid, tig);
        #pragma unroll
        for (int mi = 0; mi < 2; mi++) {
            const int c2 = (m0p >> 1) + mi * 8 + gid;
            #pragma unroll
            for (int j = 0; j < 8; j++) {
                const int t = nn + j * 8 + tig * 2;
                uint2 w;
                w.x = pack2(fmaxf(acc[mi][j][0], 0.0f), fmaxf(acc[mi][j][2], 0.0f));
                w.y = pack2(fmaxf(acc[mi][j][1], 0.0f), fmaxf(acc[mi][j][3], 0.0f));
                *(uint2*)(s_y1 + c2 * AP + t) = w;
            }
        }
    }
    __syncthreads();

    // p2 (M=256, K=256), both halves -> out (fp32)
    const uint4* pkP2 = (const uint4*)(g_pk + OFF_P2) + (m0p >> 4) * 512;
    float* ob = out + (size_t)b * (NCn * Ln) + t0;
    #pragma unroll
    for (int nh = 0; nh < 2; nh++) {
        const int nn = nh * 64;
        {
            const int c00 = m0p + 2 * gid;
            const float z0 = b2[c00],      z1 = b2[c00 + 1];
            const float z2 = b2[c00 + 16], z3 = b2[c00 + 17];
            #pragma unroll
            for (int j = 0; j < 8; j++) {
                acc[0][j][0] = z0; acc[0][j][1] = z0; acc[0][j][2] = z1; acc[0][j][3] = z1;
                acc[1][j][0] = z2; acc[1][j][1] = z2; acc[1][j][2] = z3; acc[1][j][3] = z3;
            }
        }
        gemm_h2(acc, s_y1, AP, 0, 16, pkP2, 512, lane, nn, gid, tig);
        #pragma unroll
        for (int mi = 0; mi < 2; mi++) {
            const int co0 = m0p + mi * 16 + 2 * gid;
            const int co1 = co0 + 1;
            #pragma unroll
            for (int j = 0; j < 8; j++) {
                const int c = nn + j * 8 + tig * 2;
                float2 w0; w0.x = acc[mi][j][0]; w0.y = acc[mi][j][1];
                float2 w1; w1.x = acc[mi][j][2]; w1.y = acc[mi][j][3];
                *(float2*)(ob + co0 * Ln + c) = w0;
                *(float2*)(ob + co1 * Ln + c) = w1;
            }
        }
    }
}

} // anonymous namespace

// ---------------------------------------------------------------------------
extern "C" void kernel_launch(void* const* d_in, const int* in_sizes, int n_in,
                              void* d_out, int out_size)
{
    (void)in_sizes; (void)n_in; (void)out_size;
    const float* x          = (const float*)d_in[0];
    const float* mels       = (const float*)d_in[1];
    const float* input_w    = (const float*)d_in[2];
    const float* input_b    = (const float*)d_in[3];
    const float* mel_w      = (const float*)d_in[4];
    const float* mel_b      = (const float*)d_in[5];
    const float* blk_dil_w  = (const float*)d_in[6];
    const float* blk_dil_b  = (const float*)d_in[7];
    const float* blk_cond_w = (const float*)d_in[8];
    const float* blk_cond_b = (const float*)d_in[9];
    const float* blk_skip_w = (const float*)d_in[10];
    const float* blk_skip_b = (const float*)d_in[11];
    const float* blk_res_w  = (const float*)d_in[12];
    const float* blk_res_b  = (const float*)d_in[13];
    const float* post1_w    = (const float*)d_in[14];
    const float* post1_b    = (const float*)d_in[15];
    const float* post2_w    = (const float*)d_in[16];
    const float* post2_b    = (const float*)d_in[17];

    static int ngrid = 0;
    if (ngrid == 0) {
        cudaFuncSetAttribute(persist_kernel, cudaFuncAttributeMaxDynamicSharedMemorySize, BLK_SMEM);
        cudaFuncSetAttribute(sp_kernel,      cudaFuncAttributeMaxDynamicSharedMemorySize, SP_SMEM);
        int nb = 0;
        cudaOccupancyMaxActiveBlocksPerMultiprocessor(&nb, persist_kernel, 256, BLK_SMEM);
        int dev = 0, smc = 0;
        cudaGetDevice(&dev);
        cudaDeviceGetAttribute(&smc, cudaDevAttrMultiProcessorCount, dev);
        ngrid = nb * smc;
        if (ngrid <= 0) ngrid = 148;
        if (ngrid > TOTAL_TASKS) ngrid = TOTAL_TASKS;
    }

    prep_kernel<<<1024, 256>>>(blk_dil_w, blk_cond_w, blk_skip_w, blk_res_w,
                               post1_w, post2_w, blk_skip_b);
    cond_kernel<<<dim3(NT, Bn), 256>>>(mels, mel_w, mel_b);
    init_kernel<<<512, 256>>>(x, input_w, input_b);

    persist_kernel<<<ngrid, 256, BLK_SMEM>>>(blk_dil_b, blk_cond_b, blk_res_b);

    sp_kernel<<<dim3(NT, Bn), 256, SP_SMEM>>>(post1_b, post2_b, (float*)d_out);
}

// round 14
// speedup vs baseline: 2.2370x; 1.5575x over previous
#include <cuda_runtime.h>
#include <cuda_fp16.h>

// ---------------------------------------------------------------------------
// WaveNet Mel2Raw — fp16 mma.m16n8k16 (fp32 accum), deferred skip,
// persistent block kernel with per-tile dependency flags, and a
// weight-stationary cond kernel (GEMM over q) replacing the 3.3 GB-traffic
// per-tile cond.
// ---------------------------------------------------------------------------

namespace {

constexpr int Bn  = 2;
constexpr int Ln  = 32512;
constexpr int Rn  = 64;
constexpr int Sn  = 128;
constexpr int NMn = 80;
constexpr int NCn = 256;
constexpr int NBn = 30;

constexpr int AP = 136;   // smem pitch in 32-bit words
constexpr int NT = 254;   // time tiles per batch
constexpr int TASKS_PER_LAYER = Bn * NT;        // 508
constexpr int TOTAL_TASKS = NBn * TASKS_PER_LAYER;

// ---- packed fp16 weight buffer (A fragments, 32-bit words) ----
constexpr int PK_DIL_BLK  = 8192;
constexpr int PK_DIL_TAP  = 4096;
constexpr int OFF_DIL     = 0;
constexpr int PK_COND_BLK = 5120;
constexpr int OFF_COND    = 245760;
constexpr int PK_SKIP_BLK = 4096;
constexpr int OFF_SKIP    = 399360;
constexpr int PK_RES_BLK  = 2048;
constexpr int OFF_RES     = 522240;
constexpr int OFF_P1      = 583680;
constexpr int OFF_P2      = 600064;
constexpr int PK_TOTAL    = 632832;

constexpr size_t RES_SLICE  = (size_t)Bn * Rn * Ln;
constexpr size_t RESH_SLICE = (size_t)Bn * (Rn / 2) * Ln;

__device__ unsigned g_pk[PK_TOTAL];
__device__ float    g_bs_sum[Sn];
__device__ float    g_wt[256 * 2 * NMn * NMn];   // [r][ci*2+tap][c], 13.1 MB

__device__ unsigned g_condH[Bn * (NMn/2) * Ln];
__device__ float    g_resF [(NBn + 1) * RES_SLICE];
__device__ unsigned g_resHs[(NBn + 1) * RESH_SLICE];
__device__ unsigned g_hH   [NBn * Bn * (Rn/2) * Ln];
__device__ int      g_flag [TOTAL_TASKS];

__device__ __forceinline__ float ex2f(float x) {
    float y; asm("ex2.approx.f32 %0, %1;" : "=f"(y) : "f"(x)); return y;
}
__device__ __forceinline__ float rcpf(float x) {
    float y; asm("rcp.approx.f32 %0, %1;" : "=f"(y) : "f"(x)); return y;
}
__device__ __forceinline__ float gate_fn(float f, float g) {
    float ef = ex2f(2.8853900817779268f * f);
    float th = 1.0f - 2.0f * rcpf(ef + 1.0f);
    float sg = rcpf(1.0f + ex2f(-1.4426950408889634f * g));
    return th * sg;
}
__device__ __forceinline__ unsigned pack2(float a, float b) {
    __half2 h = __floats2half2_rn(a, b);
    return *(unsigned*)&h;
}

__device__ __forceinline__ void cp16(unsigned* s, const unsigned* g) {
    unsigned sa = (unsigned)__cvta_generic_to_shared(s);
    asm volatile("cp.async.ca.shared.global [%0], [%1], 16;" :: "r"(sa), "l"(g));
}
__device__ __forceinline__ void cp16cg(unsigned* s, const unsigned* g) {
    unsigned sa = (unsigned)__cvta_generic_to_shared(s);
    asm volatile("cp.async.cg.shared.global [%0], [%1], 16;" :: "r"(sa), "l"(g));
}
__device__ __forceinline__ void cp_commit() { asm volatile("cp.async.commit_group;"); }
__device__ __forceinline__ void cp_wait0()  { asm volatile("cp.async.wait_group 0;"); }

__device__ __forceinline__ void mmah(float c[4], const unsigned a[4], const unsigned b[2]) {
    asm volatile(
        "mma.sync.aligned.m16n8k16.row.col.f32.f16.f16.f32 "
        "{%0,%1,%2,%3},{%4,%5,%6,%7},{%8,%9},{%0,%1,%2,%3};"
        : "+f"(c[0]), "+f"(c[1]), "+f"(c[2]), "+f"(c[3])
        : "r"(a[0]), "r"(a[1]), "r"(a[2]), "r"(a[3]), "r"(b[0]), "r"(b[1]));
}

__device__ __forceinline__ void gemm_h2(
    float acc[2][8][4], const unsigned* __restrict__ sB, int pitch,
    int rb, int nk, const uint4* __restrict__ pkA, int miStride,
    int lane, int n0, int gid, int tig)
{
    #pragma unroll
    for (int ks = 0; ks < nk; ks++) {
        uint4 va0 = pkA[ks * 32 + lane];
        uint4 va1 = pkA[miStride + ks * 32 + lane];
        unsigned A0[4] = {va0.x, va0.y, va0.z, va0.w};
        unsigned A1[4] = {va1.x, va1.y, va1.z, va1.w};
        const unsigned* b0 = sB + (rb + ks * 8 + tig) * pitch + n0 + gid;
        const unsigned* b1 = b0 + 4 * pitch;
        #pragma unroll
        for (int j = 0; j < 8; j++) {
            unsigned bf[2] = { b0[j * 8], b1[j * 8] };
            mmah(acc[0][j], A0, bf);
            mmah(acc[1][j], A1, bf);
        }
    }
}

__device__ __forceinline__ void gemm_h1(
    float acc[8][4], const unsigned* __restrict__ sB, int pitch,
    int rb, int nk, const uint4* __restrict__ pkA,
    int lane, int n0, int gid, int tig)
{
    #pragma unroll
    for (int ks = 0; ks < nk; ks++) {
        uint4 va = pkA[ks * 32 + lane];
        unsigned A[4] = {va.x, va.y, va.z, va.w};
        const unsigned* b0 = sB + (rb + ks * 8 + tig) * pitch + n0 + gid;
        const unsigned* b1 = b0 + 4 * pitch;
        #pragma unroll
        for (int j = 0; j < 8; j++) {
            unsigned bf[2] = { b0[j * 8], b1[j * 8] };
            mmah(acc[j], A, bf);
        }
    }
}

// ---------------------------------------------------------------------------
// prep: pack weights into fp16 A fragments + skip-bias sum + cond transpose
// ---------------------------------------------------------------------------
__device__ __forceinline__ uint4 pack_frag_h(const float* __restrict__ src,
                                             int as, int am, int ao,
                                             int nk, int idx4)
{
    const int mt   = idx4 / (nk * 32);
    const int rem  = idx4 % (nk * 32);
    const int ks   = rem >> 5;
    const int lane = rem & 31;
    const int gid  = lane >> 2, tig = lane & 3;
    const int r0 = mt * 16 + 2 * gid;
    const int r1 = r0 + 1;
    const int k  = ks * 16 + 2 * tig;
    uint4 v;
    v.x = pack2(src[r0 * as + k * am + ao],       src[r0 * as + (k + 1) * am + ao]);
    v.y = pack2(src[r1 * as + k * am + ao],       src[r1 * as + (k + 1) * am + ao]);
    v.z = pack2(src[r0 * as + (k + 8) * am + ao], src[r0 * as + (k + 9) * am + ao]);
    v.w = pack2(src[r1 * as + (k + 8) * am + ao], src[r1 * as + (k + 9) * am + ao]);
    return v;
}

__global__ void prep_kernel(
    const float* __restrict__ dil_w,  const float* __restrict__ cond_w,
    const float* __restrict__ skip_w, const float* __restrict__ res_w,
    const float* __restrict__ p1_w,   const float* __restrict__ p2_w,
    const float* __restrict__ skip_b, const float* __restrict__ mel_w)
{
    uint4* pk = (uint4*)g_pk;
    const int stride = gridDim.x * blockDim.x;
    const int g0 = blockIdx.x * blockDim.x + threadIdx.x;
    if (g0 < Sn) {
        float s = 0.0f;
        for (int i = 0; i < NBn; i++) s += skip_b[i * Sn + g0];
        g_bs_sum[g0] = s;
    }
    for (int q = g0; q < PK_TOTAL / 4; q += stride) {
        uint4 v;
        if (q < OFF_COND / 4) {
            const int blk = q / (PK_DIL_BLK / 4), r2 = q % (PK_DIL_BLK / 4);
            const int tap = r2 / (PK_DIL_TAP / 4), idx4 = r2 % (PK_DIL_TAP / 4);
            v = pack_frag_h(dil_w + blk * 16384, 128, 2, tap, 4, idx4);
        } else if (q < OFF_SKIP / 4) {
            const int q2 = q - OFF_COND / 4;
            const int blk = q2 / (PK_COND_BLK / 4), idx4 = q2 % (PK_COND_BLK / 4);
            v = pack_frag_h(cond_w + blk * (128 * NMn), NMn, 1, 0, 5, idx4);
        } else if (q < OFF_RES / 4) {
            const int q2 = q - OFF_SKIP / 4;
            const int blk = q2 / (PK_SKIP_BLK / 4), idx4 = q2 % (PK_SKIP_BLK / 4);
            v = pack_frag_h(skip_w + blk * (Sn * Rn), 64, 1, 0, 4, idx4);
        } else if (q < OFF_P1 / 4) {
            const int q2 = q - OFF_RES / 4;
            const int blk = q2 / (PK_RES_BLK / 4), idx4 = q2 % (PK_RES_BLK / 4);
            v = pack_frag_h(res_w + blk * (Rn * Rn), 64, 1, 0, 4, idx4);
        } else if (q < OFF_P2 / 4) {
            v = pack_frag_h(p1_w, 128, 1, 0, 8, q - OFF_P1 / 4);
        } else {
            v = pack_frag_h(p2_w, 256, 1, 0, 16, q - OFF_P2 / 4);
        }
        pk[q] = v;
    }
    // transpose mel_w -> g_wt[r][ci*2+tap][c]
    for (int i = g0; i < 256 * 2 * NMn * NMn; i += stride) {
        const int r   = i / (2 * NMn * NMn);
        const int rem = i % (2 * NMn * NMn);
        const int kk  = rem / NMn;
        const int c   = rem % NMn;
        const int ci  = kk >> 1;
        const int tap = kk & 1;
        g_wt[i] = mel_w[(c * NMn + ci) * 512 + 255 - r + tap * 256];
    }
}

// ---------------------------------------------------------------------------
// cond (weight-stationary): grid (256 r, Bn). For fixed r:
//   cond[c, 256q+r] = mel_b[c] + sum_ci W0_r[c,ci] m[ci,q] + W1_r[c,ci] m[ci,q+1]
// ---------------------------------------------------------------------------
constexpr int CD_MP   = 132;                        // s_m pitch
constexpr int CD_SMEM = (NMn * CD_MP + 2 * NMn * NMn) * 4;   // 93440 B

__global__ __launch_bounds__(256, 2) void cond_kernel(
    const float* __restrict__ mels, const float* __restrict__ mel_b)
{
    extern __shared__ float smf[];
    float* s_m = smf;                   // [80][132] (mel frames)
    float* s_w = smf + NMn * CD_MP;     // [160][80] (this r's weights)

    const int r   = blockIdx.x;
    const int b   = blockIdx.y;
    const int tid = threadIdx.x;

    for (int i = tid; i < NMn * 128; i += 256) {
        const int ci = i >> 7, q = i & 127;
        s_m[ci * CD_MP + q] = mels[(b * NMn + ci) * 128 + q];
    }
    for (int i = tid; i < NMn * 4; i += 256) {          // zero pad cols 128..131
        const int ci = i >> 2, k = i & 3;
        s_m[ci * CD_MP + 128 + k] = 0.0f;
    }
    const float* wr = g_wt + (size_t)r * (2 * NMn * NMn);
    for (int i = tid; i < 2 * NMn * NMn; i += 256) s_w[i] = wr[i];
    __syncthreads();

    // 320 items: qb (fast, 16) x cg (20); each item = 4 c x 8 q
    for (int it = tid; it < 320; it += 256) {
        const int qb = it & 15, cg = it >> 4;
        const int c0 = cg * 4, q0 = qb * 8;

        float acc[4][8];
        #pragma unroll
        for (int c = 0; c < 4; c++) {
            const float bias = mel_b[c0 + c];
            #pragma unroll
            for (int j = 0; j < 8; j++) acc[c][j] = bias;
        }

        for (int ci = 0; ci < NMn; ci++) {
            float mq[9];
            const float* mrow = s_m + ci * CD_MP + q0;
            float4 mv0 = *(const float4*)(mrow);
            float4 mv1 = *(const float4*)(mrow + 4);
            mq[0] = mv0.x; mq[1] = mv0.y; mq[2] = mv0.z; mq[3] = mv0.w;
            mq[4] = mv1.x; mq[5] = mv1.y; mq[6] = mv1.z; mq[7] = mv1.w;
            mq[8] = mrow[8];
            float4 w0 = *(const float4*)(s_w + (2 * ci) * NMn + c0);
            float4 w1 = *(const float4*)(s_w + (2 * ci + 1) * NMn + c0);
            const float w0v[4] = {w0.x, w0.y, w0.z, w0.w};
            const float w1v[4] = {w1.x, w1.y, w1.z, w1.w};
            #pragma unroll
            for (int c = 0; c < 4; c++)
                #pragma unroll
                for (int j = 0; j < 8; j++)
                    acc[c][j] += w0v[c] * mq[j] + w1v[c] * mq[j + 1];
        }

        unsigned* out0 = g_condH + (size_t)(b * (NMn / 2) + (c0 >> 1)) * Ln;
        unsigned* out1 = out0 + Ln;
        #pragma unroll
        for (int j = 0; j < 8; j++) {
            const int q = q0 + j;
            if (q < 127) {
                const int t = q * 256 + r;
                out0[t] = pack2(acc[0][j], acc[1][j]);
                out1[t] = pack2(acc[2][j], acc[3][j]);
            }
        }
    }
}

__global__ void init_kernel(const float* __restrict__ x,
                            const float* __restrict__ iw,
                            const float* __restrict__ ib)
{
    const int stride = gridDim.x * blockDim.x;
    const int tid0   = blockIdx.x * blockDim.x + threadIdx.x;
    for (int i = tid0; i < Bn * (Rn / 2) * Ln; i += stride) {
        const int t  = i % Ln;
        const int c2 = (i / Ln) % (Rn / 2);
        const int b  = i / (Ln * (Rn / 2));
        const float xv = x[b * Ln + t];
        const float v0 = iw[2 * c2] * xv + ib[2 * c2];
        const float v1 = iw[2 * c2 + 1] * xv + ib[2 * c2 + 1];
        g_resF[(size_t)(b * Rn + 2 * c2) * Ln + t]     = v0;
        g_resF[(size_t)(b * Rn + 2 * c2 + 1) * Ln + t] = v1;
        g_resHs[i] = pack2(v0, v1);
    }
    for (int i = tid0; i < TOTAL_TASKS; i += stride) g_flag[i] = 0;
}

// ---------------------------------------------------------------------------
// Persistent block kernel: all 30 layers pipelined via per-tile flags.
// ---------------------------------------------------------------------------
constexpr int BLK_SMEM = 104 * AP * 4;   // 56576 B -> 2 CTAs/SM

__global__ __launch_bounds__(256, 2) void persist_kernel(
    const float* __restrict__ dil_b, const float* __restrict__ cond_b,
    const float* __restrict__ res_b)
{
    extern __shared__ unsigned smu[];
    unsigned* s_act = smu;
    unsigned* s_h   = smu;

    const int tid  = threadIdx.x;
    const int lane = tid & 31, warp = tid >> 5;
    const int gid  = lane >> 2, tig = lane & 3;
    const int mw   = warp & 3;
    const int n0   = (warp >> 2) * 64;
    const int m0f  = mw * 16;

    for (int T = blockIdx.x; T < TOTAL_TASKS; T += gridDim.x) {
        const int l  = T / TASKS_PER_LAYER;
        const int j  = T % TASKS_PER_LAYER;
        const int b  = j / NT;
        const int kt = j % NT;
        const int t0 = kt * 128;
        const int d  = 1 << (l % 10);

        const float* bd = dil_b  + l * 128;
        const float* bc = cond_b + l * 128;
        const float* br = res_b  + l * Rn;

        const float*    res_in  = g_resF  + (size_t)l * RES_SLICE  + (size_t)b * (Rn * Ln);
        float*          res_out = g_resF  + (size_t)(l + 1) * RES_SLICE  + (size_t)b * (Rn * Ln);
        const unsigned* rh      = g_resHs + (size_t)l * RESH_SLICE + (size_t)b * ((Rn / 2) * Ln);
        unsigned*       rh_out  = g_resHs + (size_t)(l + 1) * RESH_SLICE + (size_t)b * ((Rn / 2) * Ln);

        if (l > 0) {
            if (tid == 0) {
                const int base = (l - 1) * TASKS_PER_LAYER + b * NT;
                int k0 = kt - 4; if (k0 < 0) k0 = 0;
                for (int k = kt; k >= k0; k--) {
                    while (atomicAdd(&g_flag[base + k], 0) == 0) __nanosleep(64);
                }
                __threadfence();
            }
            __syncthreads();
        }

        for (int i = tid; i < 32 * 32; i += 256) {
            const int row = i >> 5, q = (i & 31) * 4;
            cp16cg(s_act + (32 + row) * AP + q, rh + row * Ln + t0 + q);
        }
        const unsigned* ch = g_condH + b * ((NMn / 2) * Ln);
        for (int i = tid; i < 40 * 32; i += 256) {
            const int row = i >> 5, q = (i & 31) * 4;
            cp16(s_act + (64 + row) * AP + q, ch + row * Ln + t0 + q);
        }
        if (t0 >= d) {
            const unsigned* rp = rh + t0 - d;
            if ((d & 3) == 0) {
                for (int i = tid; i < 32 * 32; i += 256) {
                    const int row = i >> 5, q = (i & 31) * 4;
                    cp16cg(s_act + row * AP + q, rp + row * Ln + q);
                }
            } else if (d == 2) {
                for (int i = tid; i < 32 * 64; i += 256) {
                    const int row = i >> 6, q = (i & 63) * 2;
                    uint2 v = __ldcg((const uint2*)(rp + row * Ln + q));
                    *(uint2*)(s_act + row * AP + q) = v;
                }
            } else {
                for (int i = tid; i < 32 * 128; i += 256) {
                    const int row = i >> 7, q = i & 127;
                    s_act[row * AP + q] = __ldcg(rp + row * Ln + q);
                }
            }
        } else {
            for (int i = tid; i < 32 * 128; i += 256) {
                const int row = i >> 7, tt = i & 127;
                const int tp = t0 + tt - d;
                s_act[row * AP + tt] = (tp >= 0) ? __ldcg(rh + row * Ln + tp) : 0u;
            }
        }
        cp_commit();
        cp_wait0();
        __syncthreads();

        float acc[2][8][4];
        {
            const int cf0 = m0f + 2 * gid, cf1 = cf0 + 1;
            const float f0 = bd[cf0] + bc[cf0],           f1 = bd[cf1] + bc[cf1];
            const float g0 = bd[cf0 + 64] + bc[cf0 + 64], g1 = bd[cf1 + 64] + bc[cf1 + 64];
            #pragma unroll
            for (int jj = 0; jj < 8; jj++) {
                acc[0][jj][0] = f0; acc[0][jj][1] = f0; acc[0][jj][2] = f1; acc[0][jj][3] = f1;
                acc[1][jj][0] = g0; acc[1][jj][1] = g0; acc[1][jj][2] = g1; acc[1][jj][3] = g1;
            }
        }
        const uint4* pk_dil = (const uint4*)(g_pk + OFF_DIL + l * PK_DIL_BLK);
        const uint4* pk_c   = (const uint4*)(g_pk + OFF_COND + l * PK_COND_BLK);
        gemm_h2(acc, s_act, AP,  0, 4, pk_dil + mw * 128,        4 * 128, lane, n0, gid, tig);
        gemm_h2(acc, s_act, AP, 32, 4, pk_dil + 1024 + mw * 128, 4 * 128, lane, n0, gid, tig);
        gemm_h2(acc, s_act, AP, 64, 5, pk_c + mw * 160,          4 * 160, lane, n0, gid, tig);

        __syncthreads();

        {
            const int c2r = (m0f >> 1) + gid;
            #pragma unroll
            for (int jj = 0; jj < 8; jj++) {
                const int t = n0 + jj * 8 + tig * 2;
                uint2 w;
                w.x = pack2(gate_fn(acc[0][jj][0], acc[1][jj][0]),
                            gate_fn(acc[0][jj][2], acc[1][jj][2]));
                w.y = pack2(gate_fn(acc[0][jj][1], acc[1][jj][1]),
                            gate_fn(acc[0][jj][3], acc[1][jj][3]));
                *(uint2*)(s_h + c2r * AP + t) = w;
            }
        }
        __syncthreads();

        {
            unsigned* ho = g_hH + (size_t)(l * Bn + b) * ((Rn / 2) * Ln) + t0;
            for (int i = tid; i < 32 * 32; i += 256) {
                const int row = i >> 5, q = (i & 31) * 4;
                *(uint4*)(ho + row * Ln + q) = *(const uint4*)(s_h + row * AP + q);
            }
        }

        float accr[8][4];
        const int mr = mw * 16;
        {
            const int r0 = mr + 2 * gid, r1 = r0 + 1;
            const float z0 = br[r0], z1 = br[r1];
            #pragma unroll
            for (int jj = 0; jj < 8; jj++) {
                accr[jj][0] = z0; accr[jj][1] = z0;
                accr[jj][2] = z1; accr[jj][3] = z1;
            }
        }
        const uint4* pk_r = (const uint4*)(g_pk + OFF_RES + l * PK_RES_BLK);
        gemm_h1(accr, s_h, AP, 0, 4, pk_r + (mr >> 4) * 128, lane, n0, gid, tig);

        {
            const float* rib = res_in  + t0;
            float*       rob = res_out + t0;
            unsigned*    rhb = rh_out + t0;
            const int r0 = mr + 2 * gid, r1 = r0 + 1;
            const int rw = (mr >> 1) + gid;
            #pragma unroll
            for (int jj = 0; jj < 8; jj++) {
                const int c = n0 + jj * 8 + tig * 2;
                float2 i0 = __ldcg((const float2*)(rib + r0 * Ln + c));
                float2 i1 = __ldcg((const float2*)(rib + r1 * Ln + c));
                float v00 = i0.x + accr[jj][0];
                float v01 = i0.y + accr[jj][1];
                float v10 = i1.x + accr[jj][2];
                float v11 = i1.y + accr[jj][3];
                float2 w0; w0.x = v00; w0.y = v01;
                float2 w1; w1.x = v10; w1.y = v11;
                *(float2*)(rob + r0 * Ln + c) = w0;
                *(float2*)(rob + r1 * Ln + c) = w1;
                uint2 hw; hw.x = pack2(v00, v10); hw.y = pack2(v01, v11);
                *(uint2*)(rhb + rw * Ln + c) = hw;
            }
        }

        __threadfence();
        __syncthreads();
        if (tid == 0) atomicExch(&g_flag[T], 1);
    }
}

// ---------------------------------------------------------------------------
// Tail: skip = bias_sum + sum_i Ws_i h_i -> relu -> p1 -> relu -> p2
// ---------------------------------------------------------------------------
constexpr int SP_SMEM = (64 + 128) * AP * 4;   // 104448 B

__global__ __launch_bounds__(256, 2) void sp_kernel(
    const float* __restrict__ b1, const float* __restrict__ b2,
    float* __restrict__ out)
{
    extern __shared__ unsigned smu[];
    unsigned* s_hb = smu;
    unsigned* s_sk = smu;
    unsigned* s_y1 = smu + 64 * AP;

    const int b   = blockIdx.y;
    const int t0  = blockIdx.x * 128;
    const int tid = threadIdx.x;
    const int lane = tid & 31, warp = tid >> 5;
    const int gid = lane >> 2, tig = lane & 3;
    const int mw = warp & 3;
    const int n0 = (warp >> 2) * 64;
    const int m0s = mw * 32;

    float acc[2][8][4];
    {
        const int c00 = m0s + 2 * gid;
        const float z0 = g_bs_sum[c00],      z1 = g_bs_sum[c00 + 1];
        const float z2 = g_bs_sum[c00 + 16], z3 = g_bs_sum[c00 + 17];
        #pragma unroll
        for (int j = 0; j < 8; j++) {
            acc[0][j][0] = z0; acc[0][j][1] = z0; acc[0][j][2] = z1; acc[0][j][3] = z1;
            acc[1][j][0] = z2; acc[1][j][1] = z2; acc[1][j][2] = z3; acc[1][j][3] = z3;
        }
    }
    {
        const unsigned* hp = g_hH + (size_t)(0 * Bn + b) * ((Rn / 2) * Ln) + t0;
        for (int i = tid; i < 32 * 32; i += 256) {
            const int row = i >> 5, q = (i & 31) * 4;
            cp16(s_hb + row * AP + q, hp + row * Ln + q);
        }
        cp_commit();
        cp_wait0();
    }
    __syncthreads();

    const uint4* pk_s0 = (const uint4*)(g_pk + OFF_SKIP) + (m0s >> 4) * 128;
    for (int i = 0; i < NBn; i++) {
        if (i + 1 < NBn) {
            const unsigned* hp = g_hH + (size_t)((i + 1) * Bn + b) * ((Rn / 2) * Ln) + t0;
            unsigned* dst = s_hb + ((i + 1) & 1) * (32 * AP);
            for (int k = tid; k < 32 * 32; k += 256) {
                const int row = k >> 5, q = (k & 31) * 4;
                cp16(dst + row * AP + q, hp + row * Ln + q);
            }
            cp_commit();
        }
        gemm_h2(acc, s_hb + (i & 1) * (32 * AP), AP, 0, 4,
                pk_s0 + i * (PK_SKIP_BLK / 4), 128, lane, n0, gid, tig);
        cp_wait0();
        __syncthreads();
    }

    #pragma unroll
    for (int mi = 0; mi < 2; mi++) {
        const int c2 = (m0s >> 1) + mi * 8 + gid;
        #pragma unroll
        for (int j = 0; j < 8; j++) {
            const int t = n0 + j * 8 + tig * 2;
            uint2 w;
            w.x = pack2(fmaxf(acc[mi][j][0], 0.0f), fmaxf(acc[mi][j][2], 0.0f));
            w.y = pack2(fmaxf(acc[mi][j][1], 0.0f), fmaxf(acc[mi][j][3], 0.0f));
            *(uint2*)(s_sk + c2 * AP + t) = w;
        }
    }
    __syncthreads();

    const int m0p = warp * 32;
    const uint4* pkP1 = (const uint4*)(g_pk + OFF_P1) + (m0p >> 4) * 256;
    #pragma unroll
    for (int nh = 0; nh < 2; nh++) {
        const int nn = nh * 64;
        {
            const int c00 = m0p + 2 * gid;
            const float z0 = b1[c00],      z1 = b1[c00 + 1];
            const float z2 = b1[c00 + 16], z3 = b1[c00 + 17];
            #pragma unroll
            for (int j = 0; j < 8; j++) {
                acc[0][j][0] = z0; acc[0][j][1] = z0; acc[0][j][2] = z1; acc[0][j][3] = z1;
                acc[1][j][0] = z2; acc[1][j][1] = z2; acc[1][j][2] = z3; acc[1][j][3] = z3;
            }
        }
        gemm_h2(acc, s_sk, AP, 0, 8, pkP1, 256, lane, nn, gid, tig);
        #pragma unroll
        for (int mi = 0; mi < 2; mi++) {
            const int c2 = (m0p >> 1) + mi * 8 + gid;
            #pragma unroll
            for (int j = 0; j < 8; j++) {
                const int t = nn + j * 8 + tig * 2;
                uint2 w;
                w.x = pack2(fmaxf(acc[mi][j][0], 0.0f), fmaxf(acc[mi][j][2], 0.0f));
                w.y = pack2(fmaxf(acc[mi][j][1], 0.0f), fmaxf(acc[mi][j][3], 0.0f));
                *(uint2*)(s_y1 + c2 * AP + t) = w;
            }
        }
    }
    __syncthreads();

    const uint4* pkP2 = (const uint4*)(g_pk + OFF_P2) + (m0p >> 4) * 512;
    float* ob = out + (size_t)b * (NCn * Ln) + t0;
    #pragma unroll
    for (int nh = 0; nh < 2; nh++) {
        const int nn = nh * 64;
        {
            const int c00 = m0p + 2 * gid;
            const float z0 = b2[c00],      z1 = b2[c00 + 1];
            const float z2 = b2[c00 + 16], z3 = b2[c00 + 17];
            #pragma unroll
            for (int j = 0; j < 8; j++) {
                acc[0][j][0] = z0; acc[0][j][1] = z0; acc[0][j][2] = z1; acc[0][j][3] = z1;
                acc[1][j][0] = z2; acc[1][j][1] = z2; acc[1][j][2] = z3; acc[1][j][3] = z3;
            }
        }
        gemm_h2(acc, s_y1, AP, 0, 16, pkP2, 512, lane, nn, gid, tig);
        #pragma unroll
        for (int mi = 0; mi < 2; mi++) {
            const int co0 = m0p + mi * 16 + 2 * gid;
            const int co1 = co0 + 1;
            #pragma unroll
            for (int j = 0; j < 8; j++) {
                const int c = nn + j * 8 + tig * 2;
                float2 w0; w0.x = acc[mi][j][0]; w0.y = acc[mi][j][1];
                float2 w1; w1.x = acc[mi][j][2]; w1.y = acc[mi][j][3];
                *(float2*)(ob + co0 * Ln + c) = w0;
                *(float2*)(ob + co1 * Ln + c) = w1;
            }
        }
    }
}

} // anonymous namespace

// ---------------------------------------------------------------------------
extern "C" void kernel_launch(void* const* d_in, const int* in_sizes, int n_in,
                              void* d_out, int out_size)
{
    (void)in_sizes; (void)n_in; (void)out_size;
    const float* x          = (const float*)d_in[0];
    const float* mels       = (const float*)d_in[1];
    const float* input_w    = (const float*)d_in[2];
    const float* input_b    = (const float*)d_in[3];
    const float* mel_w      = (const float*)d_in[4];
    const float* mel_b      = (const float*)d_in[5];
    const float* blk_dil_w  = (const float*)d_in[6];
    const float* blk_dil_b  = (const float*)d_in[7];
    const float* blk_cond_w = (const float*)d_in[8];
    const float* blk_cond_b = (const float*)d_in[9];
    const float* blk_skip_w = (const float*)d_in[10];
    const float* blk_skip_b = (const float*)d_in[11];
    const float* blk_res_w  = (const float*)d_in[12];
    const float* blk_res_b  = (const float*)d_in[13];
    const float* post1_w    = (const float*)d_in[14];
    const float* post1_b    = (const float*)d_in[15];
    const float* post2_w    = (const float*)d_in[16];
    const float* post2_b    = (const float*)d_in[17];

    static int ngrid = 0;
    if (ngrid == 0) {
        cudaFuncSetAttribute(persist_kernel, cudaFuncAttributeMaxDynamicSharedMemorySize, BLK_SMEM);
        cudaFuncSetAttribute(sp_kernel,      cudaFuncAttributeMaxDynamicSharedMemorySize, SP_SMEM);
        cudaFuncSetAttribute(cond_kernel,    cudaFuncAttributeMaxDynamicSharedMemorySize, CD_SMEM);
        int nb = 0;
        cudaOccupancyMaxActiveBlocksPerMultiprocessor(&nb, persist_kernel, 256, BLK_SMEM);
        int dev = 0, smc = 0;
        cudaGetDevice(&dev);
        cudaDeviceGetAttribute(&smc, cudaDevAttrMultiProcessorCount, dev);
        ngrid = nb * smc;
        if (ngrid <= 0) ngrid = 148;
        if (ngrid > TOTAL_TASKS) ngrid = TOTAL_TASKS;
    }

    prep_kernel<<<1024, 256>>>(blk_dil_w, blk_cond_w, blk_skip_w, blk_res_w,
                               post1_w, post2_w, blk_skip_b, mel_w);
    cond_kernel<<<dim3(256, Bn), 256, CD_SMEM>>>(mels, mel_b);
    init_kernel<<<512, 256>>>(x, input_w, input_b);

    persist_kernel<<<ngrid, 256, BLK_SMEM>>>(blk_dil_b, blk_cond_b, blk_res_b);

    sp_kernel<<<dim3(NT, Bn), 256, SP_SMEM>>>(post1_b, post2_b, (float*)d_out);
}